// round 3
// baseline (speedup 1.0000x reference)
#include <cuda_runtime.h>
#include <math.h>

#define SP 16384

// ---------------- scratch (device globals; every element rewritten per call) ----------------
__device__ float d_Wc[192 * 1728];                 // composite 3x3 cn weight, [o][ci*9+tap]
__device__ float d_pad[8L * 192 * 130 * 130];      // zero-padded cn
__device__ float d_cnf[8L * 192 * SP];             // cn feature
__device__ float d_qkv1[8L * 576 * SP];            // qkv after 1x1
__device__ float d_qkvd[8L * 576 * SP];            // qkv after dw 3x3
__device__ float d_gramp[8L * 2 * 32 * 2304];      // split-K gram partials
__device__ float d_gram[2L * 32 * 2304];           // reduced grams (t=0:qk, t=1:ck)
__device__ float d_normv[8 * 192 * 4];             // per (b,c): |q|^2, |k|^2, |cn|^2, <q,cn>
__device__ float d_attn[32 * 2304];                // softmax attn per (b,h)
__device__ float d_Mmat[8 * 192 * 192];            // per-batch P * blockdiag(attn)

__device__ __forceinline__ unsigned f2tf(float f) {
    unsigned u;
    asm("cvt.rna.tf32.f32 %0, %1;" : "=r"(u) : "f"(f));
    return u;
}

__device__ __forceinline__ void mma8(float* acc, const unsigned* a, unsigned b0, unsigned b1) {
    asm volatile(
        "mma.sync.aligned.m16n8k8.row.col.f32.tf32.tf32.f32 "
        "{%0,%1,%2,%3}, {%4,%5,%6,%7}, {%8,%9}, {%0,%1,%2,%3};\n"
        : "+f"(acc[0]), "+f"(acc[1]), "+f"(acc[2]), "+f"(acc[3])
        : "r"(a[0]), "r"(a[1]), "r"(a[2]), "r"(a[3]), "r"(b0), "r"(b1));
}

// ---------------- compose W'[o][ci*9+tap] = sum_m W3[o,m,tap]*W1[m,ci] ----------------
__global__ void compose_w_kernel(const float* __restrict__ w1, const float* __restrict__ w3) {
    int o = blockIdx.x / 9, tap = blockIdx.x % 9;
    int ci = threadIdx.x;
    float acc = 0.f;
    for (int m = 0; m < 192; m++)
        acc += w3[(o * 192 + m) * 9 + tap] * w1[m * 192 + ci];
    d_Wc[o * 1728 + ci * 9 + tap] = acc;
}

// ---------------- zero-padded copy of cn: [b][c][130][130] ----------------
__global__ void pad_kernel(const float* __restrict__ cn) {
    int ww = threadIdx.x;     // 0..129
    int hh = blockIdx.x;      // 0..129
    int c = blockIdx.y;
    int b = blockIdx.z;
    float v = 0.f;
    if (hh >= 1 && hh <= 128 && ww >= 1 && ww <= 128)
        v = cn[((long)(b * 192 + c)) * SP + (hh - 1) * 128 + (ww - 1)];
    d_pad[(((long)(b * 192 + c)) * 130 + hh) * 130 + ww] = v;
}

// ---------------- tiled tf32 GEMM: C[M,16384] = A[M,K] * B[K,16384], per-batch via grid.z ----
// IM2COL=1: B is implicit im2col of d_pad (3x3 conv), k = ci*9 + (dy*3+dx)
template<int IM2COL>
__global__ void __launch_bounds__(256) gemm_tf32(
    const float* __restrict__ A, const float* __restrict__ B, float* __restrict__ C,
    int K, long sA, long sB, long sC)
{
    __shared__ unsigned As[16 * 72];
    __shared__ unsigned Bs[16 * 136];

    const int bz = blockIdx.z;
    const int n0 = blockIdx.x << 7;
    const int m0 = blockIdx.y << 6;
    const int tid = threadIdx.x;
    const float* Ab = A + (long)bz * sA;
    const float* Bb = IM2COL ? (const float*)0 : (B + (long)bz * sB);
    float* Cb = C + (long)bz * sC;

    const int am = tid >> 2, ak = (tid & 3) << 2;
    const int bk = tid >> 4, bn = (tid & 15) << 3;
    const int warp = tid >> 5, lane = tid & 31;
    const int wm = (warp >> 2) << 5, wn = (warp & 3) << 5;
    const int g = lane >> 2, tg = lane & 3;

    float acc[2][4][4];
    #pragma unroll
    for (int i = 0; i < 2; i++)
        #pragma unroll
        for (int j = 0; j < 4; j++)
            #pragma unroll
            for (int l = 0; l < 4; l++) acc[i][j][l] = 0.f;

    float ar[4];
    float br[8];

    auto loadAB = [&](int k0) {
        float4 va = *reinterpret_cast<const float4*>(Ab + (long)(m0 + am) * K + k0 + ak);
        ar[0] = va.x; ar[1] = va.y; ar[2] = va.z; ar[3] = va.w;
        if (IM2COL) {
            int k = k0 + bk;
            int ci = k / 9;
            int tap = k - ci * 9;
            int dy = tap / 3;
            int dx = tap - dy * 3;
            int s = n0 + bn;
            int hh = s >> 7, wv = s & 127;
            const float* p = d_pad + (((long)(bz * 192 + ci)) * 130 + hh + dy) * 130 + wv + dx;
            #pragma unroll
            for (int j = 0; j < 8; j++) br[j] = p[j];
        } else {
            const float* p = Bb + (long)(k0 + bk) * SP + n0 + bn;
            float4 v0 = *reinterpret_cast<const float4*>(p);
            float4 v1 = *reinterpret_cast<const float4*>(p + 4);
            br[0] = v0.x; br[1] = v0.y; br[2] = v0.z; br[3] = v0.w;
            br[4] = v1.x; br[5] = v1.y; br[6] = v1.z; br[7] = v1.w;
        }
    };
    auto storeAB = [&]() {
        #pragma unroll
        for (int j = 0; j < 4; j++) As[(ak + j) * 72 + am] = f2tf(ar[j]);
        #pragma unroll
        for (int j = 0; j < 8; j++) Bs[bk * 136 + bn + j] = f2tf(br[j]);
    };
    auto compute = [&]() {
        #pragma unroll
        for (int ks = 0; ks < 16; ks += 8) {
            unsigned afr[2][4];
            #pragma unroll
            for (int mt = 0; mt < 2; mt++) {
                int m = wm + (mt << 4);
                afr[mt][0] = As[(ks + tg) * 72 + m + g];
                afr[mt][1] = As[(ks + tg) * 72 + m + g + 8];
                afr[mt][2] = As[(ks + tg + 4) * 72 + m + g];
                afr[mt][3] = As[(ks + tg + 4) * 72 + m + g + 8];
            }
            unsigned bfr[4][2];
            #pragma unroll
            for (int nt = 0; nt < 4; nt++) {
                int n = wn + (nt << 3) + g;
                bfr[nt][0] = Bs[(ks + tg) * 136 + n];
                bfr[nt][1] = Bs[(ks + tg + 4) * 136 + n];
            }
            #pragma unroll
            for (int mt = 0; mt < 2; mt++)
                #pragma unroll
                for (int nt = 0; nt < 4; nt++)
                    mma8(acc[mt][nt], afr[mt], bfr[nt][0], bfr[nt][1]);
        }
    };

    loadAB(0);
    storeAB();
    __syncthreads();
    for (int k0 = 16; k0 < K; k0 += 16) {
        loadAB(k0);
        compute();
        __syncthreads();
        storeAB();
        __syncthreads();
    }
    compute();

    #pragma unroll
    for (int mt = 0; mt < 2; mt++)
        #pragma unroll
        for (int nt = 0; nt < 4; nt++) {
            long row = m0 + wm + (mt << 4) + g;
            int col = n0 + wn + (nt << 3) + (tg << 1);
            *reinterpret_cast<float2*>(Cb + row * SP + col) =
                make_float2(acc[mt][nt][0], acc[mt][nt][1]);
            *reinterpret_cast<float2*>(Cb + (row + 8) * SP + col) =
                make_float2(acc[mt][nt][2], acc[mt][nt][3]);
        }
}

// ---------------- depthwise 3x3 (SAME, zero pad) on qkv1 -> qkvd ----------------
__global__ void dw_kernel(const float* __restrict__ dww) {
    __shared__ float rows[3][128];
    int w = threadIdx.x;
    int h = blockIdx.x;
    int o = blockIdx.y;
    int b = blockIdx.z;
    const float* src = d_qkv1 + ((long)(b * 576 + o)) * SP;
    rows[0][w] = (h > 0) ? src[(h - 1) * 128 + w] : 0.f;
    rows[1][w] = src[h * 128 + w];
    rows[2][w] = (h < 127) ? src[(h + 1) * 128 + w] : 0.f;
    float wg[9];
    #pragma unroll
    for (int t = 0; t < 9; t++) wg[t] = __ldg(dww + o * 9 + t);
    __syncthreads();
    float acc = 0.f;
    #pragma unroll
    for (int dy = 0; dy < 3; dy++)
        #pragma unroll
        for (int dx = 0; dx < 3; dx++) {
            int ww = w + dx - 1;
            if (ww >= 0 && ww < 128)
                acc += wg[dy * 3 + dx] * rows[dy][ww];
        }
    d_qkvd[((long)(b * 576 + o)) * SP + h * 128 + w] = acc;
}

// ---------------- split-K Gram partials: per (slice,t,bh) a 48x48 block ----------------
// t=0: q · k^T ; t=1: cn · k^T
__global__ void __launch_bounds__(128) gram_kernel() {
    __shared__ unsigned Sa[32 * 56];
    __shared__ unsigned Sb[32 * 56];
    int slice = blockIdx.x;   // 0..7
    int t = blockIdx.y;       // 0..1
    int bh = blockIdx.z;      // 0..31
    int b = bh >> 2, h = bh & 3;
    const float* Arow = t ? (d_cnf + ((long)(b * 192 + h * 48)) * SP)
                          : (d_qkvd + ((long)(b * 576 + h * 48)) * SP);
    const float* Brow = d_qkvd + ((long)(b * 576 + 192 + h * 48)) * SP;
    int tid = threadIdx.x;
    int warp = tid >> 5, lane = tid & 31, g = lane >> 2, tg = lane & 3;
    float acc[6][4];
    #pragma unroll
    for (int i = 0; i < 6; i++)
        #pragma unroll
        for (int j = 0; j < 4; j++) acc[i][j] = 0.f;

    int kbase = slice * 2048;
    for (int kb = 0; kb < 2048; kb += 32) {
        __syncthreads();
        #pragma unroll
        for (int it = 0; it < 12; it++) {
            int idx = tid + it * 128;
            int m = idx >> 5, kk = idx & 31;
            Sa[kk * 56 + m] = f2tf(Arow[(long)m * SP + kbase + kb + kk]);
            Sb[kk * 56 + m] = f2tf(Brow[(long)m * SP + kbase + kb + kk]);
        }
        __syncthreads();
        if (warp < 3) {
            #pragma unroll
            for (int ks = 0; ks < 32; ks += 8) {
                unsigned a[4];
                int m = warp << 4;
                a[0] = Sa[(ks + tg) * 56 + m + g];
                a[1] = Sa[(ks + tg) * 56 + m + g + 8];
                a[2] = Sa[(ks + tg + 4) * 56 + m + g];
                a[3] = Sa[(ks + tg + 4) * 56 + m + g + 8];
                #pragma unroll
                for (int nt = 0; nt < 6; nt++) {
                    unsigned b0 = Sb[(ks + tg) * 56 + (nt << 3) + g];
                    unsigned b1 = Sb[(ks + tg + 4) * 56 + (nt << 3) + g];
                    mma8(acc[nt], a, b0, b1);
                }
            }
        }
    }
    if (warp < 3) {
        float* out = d_gramp + (((long)slice * 2 + t) * 32 + bh) * 2304;
        #pragma unroll
        for (int nt = 0; nt < 6; nt++) {
            int r = (warp << 4) + g;
            int col = (nt << 3) + (tg << 1);
            out[r * 48 + col] = acc[nt][0];
            out[r * 48 + col + 1] = acc[nt][1];
            out[(r + 8) * 48 + col] = acc[nt][2];
            out[(r + 8) * 48 + col + 1] = acc[nt][3];
        }
    }
}

// deterministic reduction of the 8 split-K slices
__global__ void gram_reduce_kernel() {
    int idx = blockIdx.x * 256 + threadIdx.x;
    if (idx < 2 * 32 * 2304) {
        float s = 0.f;
        #pragma unroll
        for (int p = 0; p < 8; p++) s += d_gramp[(long)p * (2 * 32 * 2304) + idx];
        d_gram[idx] = s;
    }
}

// ---------------- per-(b,c) norms + <q,cn> ----------------
__global__ void diag_kernel() {
    int bc = blockIdx.x;   // b*192 + c
    int b = bc / 192;
    const float* q = d_qkvd + ((long)(b * 576 + (bc - b * 192))) * SP;
    const float* k = q + 192L * SP;
    const float* cn = d_cnf + ((long)bc) * SP;
    float s0 = 0, s1 = 0, s2 = 0, s3 = 0;
    for (int i = threadIdx.x; i < SP; i += 256) {
        float qv = q[i], kv = k[i], cv = cn[i];
        s0 += qv * qv; s1 += kv * kv; s2 += cv * cv; s3 += qv * cv;
    }
    __shared__ float red[4][256];
    int tid = threadIdx.x;
    red[0][tid] = s0; red[1][tid] = s1; red[2][tid] = s2; red[3][tid] = s3;
    __syncthreads();
    for (int off = 128; off > 0; off >>= 1) {
        if (tid < off) {
            #pragma unroll
            for (int j = 0; j < 4; j++) red[j][tid] += red[j][tid + off];
        }
        __syncthreads();
    }
    if (tid < 4) d_normv[bc * 4 + tid] = red[tid][0];
}

// ---------------- logits + softmax -> attn ----------------
__global__ void attn_kernel(const float* __restrict__ temp) {
    int bh = blockIdx.x;
    int b = bh >> 2, h = bh & 3;
    __shared__ float L[48][49];
    __shared__ float qn[48], kn[48], cnn[48], un[48];
    int tid = threadIdx.x;
    if (tid < 48) {
        int bc = b * 192 + h * 48 + tid;
        float nq = d_normv[bc * 4 + 0];
        float nk = d_normv[bc * 4 + 1];
        float nc = d_normv[bc * 4 + 2];
        float dqc = d_normv[bc * 4 + 3];
        float q_n = fmaxf(sqrtf(nq), 1e-12f);
        float k_n = fmaxf(sqrtf(nk), 1e-12f);
        float c_n = fmaxf(sqrtf(nc), 1e-12f);
        float uu = 2.f + 2.f * dqc / (q_n * c_n);   // ||q_hat + cn_hat||^2
        float u_n = fmaxf(sqrtf(fmaxf(uu, 0.f)), 1e-12f);
        qn[tid] = q_n; kn[tid] = k_n; cnn[tid] = c_n; un[tid] = u_n;
    }
    __syncthreads();
    const float* Gqk = d_gram + (long)bh * 2304;
    const float* Gck = d_gram + (long)(32 + bh) * 2304;
    float tp = temp[h];
    for (int idx = tid; idx < 2304; idx += 256) {
        int c = idx / 48, d = idx - c * 48;
        L[c][d] = (Gqk[idx] / qn[c] + Gck[idx] / cnn[c]) / (un[c] * kn[d]) * tp;
    }
    __syncthreads();
    if (tid < 48) {
        float mx = -1e30f;
        #pragma unroll
        for (int d = 0; d < 48; d++) mx = fmaxf(mx, L[tid][d]);
        float e[48];
        float sum = 0.f;
        #pragma unroll
        for (int d = 0; d < 48; d++) { e[d] = expf(L[tid][d] - mx); sum += e[d]; }
        float inv = 1.f / sum;
        #pragma unroll
        for (int d = 0; d < 48; d++)
            d_attn[(long)bh * 2304 + tid * 48 + d] = e[d] * inv;
    }
}

// ---------------- M_b = P * blockdiag(attn_b)  (192x192 per batch) ----------------
__global__ void mker_kernel(const float* __restrict__ P) {
    int b = blockIdx.x;
    int idx = blockIdx.y * 256 + threadIdx.x;  // < 36864
    int o = idx / 192, j = idx - o * 192;
    int h = j / 48, d = j - h * 48;
    const float* att = d_attn + ((long)(b * 4 + h)) * 2304 + d;
    const float* pw = P + o * 192 + h * 48;
    float acc = 0.f;
    #pragma unroll
    for (int c2 = 0; c2 < 48; c2++) acc += pw[c2] * att[c2 * 48];
    d_Mmat[(long)b * 36864 + idx] = acc;
}

// ---------------- launch ----------------
extern "C" void kernel_launch(void* const* d_in, const int* in_sizes, int n_in,
                              void* d_out, int out_size) {
    const float* x     = (const float*)d_in[0];
    const float* cn    = (const float*)d_in[1];
    const float* w1    = (const float*)d_in[2];
    const float* w3    = (const float*)d_in[3];
    const float* qkvw  = (const float*)d_in[4];
    const float* dww   = (const float*)d_in[5];
    const float* projw = (const float*)d_in[6];
    const float* temp  = (const float*)d_in[7];
    float* out = (float*)d_out;

    float *pWc, *pCnf, *pQkv1, *pQkvd, *pM;
    cudaGetSymbolAddress((void**)&pWc, d_Wc);
    cudaGetSymbolAddress((void**)&pCnf, d_cnf);
    cudaGetSymbolAddress((void**)&pQkv1, d_qkv1);
    cudaGetSymbolAddress((void**)&pQkvd, d_qkvd);
    cudaGetSymbolAddress((void**)&pM, d_Mmat);

    compose_w_kernel<<<1728, 192>>>(w1, w3);
    pad_kernel<<<dim3(130, 192, 8), 130>>>(cn);
    // cn_f = composite 3x3 conv (implicit im2col GEMM), K = 192*9
    gemm_tf32<1><<<dim3(128, 3, 8), 256>>>(pWc, (const float*)0, pCnf,
                                           1728, 0, 0, 192L * SP);
    // qkv1 = 1x1 conv, M=576 K=192
    gemm_tf32<0><<<dim3(128, 9, 8), 256>>>(qkvw, x, pQkv1,
                                           192, 0, 192L * SP, 576L * SP);
    dw_kernel<<<dim3(128, 576, 8), 128>>>(dww);
    gram_kernel<<<dim3(8, 2, 32), 128>>>();
    gram_reduce_kernel<<<576, 256>>>();
    diag_kernel<<<1536, 256>>>();
    attn_kernel<<<32, 256>>>(temp);
    mker_kernel<<<dim3(8, 144), 256>>>(projw);
    // out = M_b @ v  (v = qkvd channels 384..575)
    gemm_tf32<0><<<dim3(128, 3, 8), 256>>>(pM, pQkvd + 384L * SP, out,
                                           192, 192L * 192, 576L * SP, 192L * SP);
}

// round 5
// speedup vs baseline: 1.1865x; 1.1865x over previous
#include <cuda_runtime.h>
#include <math.h>

#define SP 16384

// ---------------- scratch (device globals; every element rewritten per call) ----------------
__device__ float d_Wc[192 * 1728];                 // composite 3x3 cn weight, [o][ci*9+tap]
__device__ float d_pad[8L * 192 * 130 * 130];      // zero-padded cn
__device__ float d_cnf[8L * 192 * SP];             // cn feature
__device__ float d_qkv1[8L * 576 * SP];            // qkv after 1x1
__device__ float d_qkvd[8L * 576 * SP];            // qkv after dw 3x3
__device__ float d_gramp[8L * 2 * 32 * 2304];      // split-K gram partials
__device__ float d_gram[2L * 32 * 2304];           // reduced grams (t=0:qk, t=1:ck)
__device__ float d_normv[8 * 192 * 4];             // per (b,c): |q|^2, |k|^2, |cn|^2, <q,cn>
__device__ float d_attn[32 * 2304];                // softmax attn per (b,h)
__device__ float d_Mmat[8 * 192 * 192];            // per-batch P * blockdiag(attn)

__device__ __forceinline__ unsigned f2tf(float f) {
    unsigned u;
    asm("cvt.rna.tf32.f32 %0, %1;" : "=r"(u) : "f"(f));
    return u;
}

__device__ __forceinline__ void mma8(float* acc, const unsigned* a, unsigned b0, unsigned b1) {
    asm volatile(
        "mma.sync.aligned.m16n8k8.row.col.f32.tf32.tf32.f32 "
        "{%0,%1,%2,%3}, {%4,%5,%6,%7}, {%8,%9}, {%0,%1,%2,%3};\n"
        : "+f"(acc[0]), "+f"(acc[1]), "+f"(acc[2]), "+f"(acc[3])
        : "r"(a[0]), "r"(a[1]), "r"(a[2]), "r"(a[3]), "r"(b0), "r"(b1));
}

__device__ __forceinline__ void cpa16(float* smem, const float* g) {
    unsigned d = (unsigned)__cvta_generic_to_shared(smem);
    asm volatile("cp.async.cg.shared.global [%0], [%1], 16;\n" :: "r"(d), "l"(g));
}
__device__ __forceinline__ void cpa4(float* smem, const float* g) {
    unsigned d = (unsigned)__cvta_generic_to_shared(smem);
    asm volatile("cp.async.ca.shared.global [%0], [%1], 4;\n" :: "r"(d), "l"(g));
}

// ---------------- compose W'[o][ci*9+tap] = sum_m W3[o,m,tap]*W1[m,ci] ----------------
__global__ void compose_w_kernel(const float* __restrict__ w1, const float* __restrict__ w3) {
    int o = blockIdx.x / 9, tap = blockIdx.x % 9;
    int ci = threadIdx.x;
    float acc = 0.f;
    for (int m = 0; m < 192; m++)
        acc += w3[(o * 192 + m) * 9 + tap] * w1[m * 192 + ci];
    d_Wc[o * 1728 + ci * 9 + tap] = acc;
}

// ---------------- zero-padded copy of cn: [b][c][130][130] ----------------
__global__ void pad_kernel(const float* __restrict__ cn) {
    int ww = threadIdx.x;     // 0..129
    int hh = blockIdx.x;      // 0..129
    int c = blockIdx.y;
    int b = blockIdx.z;
    float v = 0.f;
    if (hh >= 1 && hh <= 128 && ww >= 1 && ww <= 128)
        v = cn[((long)(b * 192 + c)) * SP + (hh - 1) * 128 + (ww - 1)];
    d_pad[(((long)(b * 192 + c)) * 130 + hh) * 130 + ww] = v;
}

// ---------------- tf32 GEMM v2: C[M,16384] = A[M,K] * B[K,16384] per batch ----------------
// Block 96(M) x 128(N) x 16(K), 128 threads = 4 warps, warp tile 48x64 (mt=3, nt=8).
// Double-buffered smem, cp.async loads, one __syncthreads per K-tile.
// IM2COL=1: B is implicit im2col of d_pad (3x3 conv), k = ci*9 + tap
template<int IM2COL>
__global__ void __launch_bounds__(128, 3) gemm_v2(
    const float* __restrict__ A, const float* __restrict__ B, float* __restrict__ C,
    int K, long sA, long sB, long sC)
{
    __shared__ float As[2][96 * 20];   // [m][k], row stride 20 (conflict-free)
    __shared__ float Bs[2][16 * 136];  // [k][n], row stride 136

    const int bz = blockIdx.z;
    const int n0 = blockIdx.x << 7;
    const int m0 = blockIdx.y * 96;
    const int tid = threadIdx.x;
    const float* Ab = A + (long)bz * sA;
    const float* Bb = IM2COL ? (const float*)0 : (B + (long)bz * sB);
    float* Cb = C + (long)bz * sC;

    const int ar = tid >> 2;            // 0..31
    const int akq = (tid & 3) << 2;     // 0,4,8,12
    const int bk = tid >> 4;            // 0..7
    const int bn = (tid & 15) << 3;     // 0..120
    const int warp = tid >> 5, lane = tid & 31;
    const int wm = (warp >> 1) * 48;
    const int wn = (warp & 1) << 6;
    const int g = lane >> 2, tg = lane & 3;

    float acc[3][8][4];
    #pragma unroll
    for (int i = 0; i < 3; i++)
        #pragma unroll
        for (int j = 0; j < 8; j++)
            #pragma unroll
            for (int l = 0; l < 4; l++) acc[i][j][l] = 0.f;

    auto issue = [&](int t, int buf) {
        int k0 = t << 4;
        #pragma unroll
        for (int i = 0; i < 3; i++) {
            int r = ar + (i << 5);
            cpa16(&As[buf][r * 20 + akq], Ab + (long)(m0 + r) * K + k0 + akq);
        }
        #pragma unroll
        for (int i = 0; i < 2; i++) {
            int kr = bk + (i << 3);
            if (IM2COL) {
                int k = k0 + kr;
                int ci = k / 9;
                int tap = k - ci * 9;
                int dy = tap / 3;
                int dx = tap - dy * 3;
                int s = n0 + bn;
                int hh = s >> 7, wv = s & 127;
                const float* p = d_pad + (((long)(bz * 192 + ci)) * 130 + hh + dy) * 130 + wv + dx;
                #pragma unroll
                for (int j = 0; j < 8; j++)
                    cpa4(&Bs[buf][kr * 136 + bn + j], p + j);
            } else {
                const float* p = Bb + (long)(k0 + kr) * SP + n0 + bn;
                cpa16(&Bs[buf][kr * 136 + bn], p);
                cpa16(&Bs[buf][kr * 136 + bn + 4], p + 4);
            }
        }
        asm volatile("cp.async.commit_group;\n");
    };

    auto compute = [&](int buf) {
        #pragma unroll
        for (int ks = 0; ks < 16; ks += 8) {
            unsigned af[3][4];
            #pragma unroll
            for (int mt = 0; mt < 3; mt++) {
                int m = wm + (mt << 4);
                af[mt][0] = f2tf(As[buf][(m + g) * 20 + ks + tg]);
                af[mt][1] = f2tf(As[buf][(m + g + 8) * 20 + ks + tg]);
                af[mt][2] = f2tf(As[buf][(m + g) * 20 + ks + tg + 4]);
                af[mt][3] = f2tf(As[buf][(m + g + 8) * 20 + ks + tg + 4]);
            }
            #pragma unroll
            for (int nt = 0; nt < 8; nt++) {
                int n = wn + (nt << 3) + g;
                unsigned b0 = f2tf(Bs[buf][(ks + tg) * 136 + n]);
                unsigned b1 = f2tf(Bs[buf][(ks + tg + 4) * 136 + n]);
                #pragma unroll
                for (int mt = 0; mt < 3; mt++)
                    mma8(acc[mt][nt], af[mt], b0, b1);
            }
        }
    };

    const int T = K >> 4;
    issue(0, 0);
    for (int t = 0; t < T; t++) {
        asm volatile("cp.async.wait_group 0;\n");
        __syncthreads();
        if (t + 1 < T) issue(t + 1, (t + 1) & 1);
        compute(t & 1);
    }

    #pragma unroll
    for (int mt = 0; mt < 3; mt++)
        #pragma unroll
        for (int nt = 0; nt < 8; nt++) {
            long row = m0 + wm + (mt << 4) + g;
            int col = n0 + wn + (nt << 3) + (tg << 1);
            *reinterpret_cast<float2*>(Cb + row * SP + col) =
                make_float2(acc[mt][nt][0], acc[mt][nt][1]);
            *reinterpret_cast<float2*>(Cb + (row + 8) * SP + col) =
                make_float2(acc[mt][nt][2], acc[mt][nt][3]);
        }
}

// ---------------- depthwise 3x3 (SAME, zero pad) on qkv1 -> qkvd ----------------
__global__ void dw_kernel(const float* __restrict__ dww) {
    __shared__ float rows[3][128];
    int w = threadIdx.x;
    int h = blockIdx.x;
    int o = blockIdx.y;
    int b = blockIdx.z;
    const float* src = d_qkv1 + ((long)(b * 576 + o)) * SP;
    rows[0][w] = (h > 0) ? src[(h - 1) * 128 + w] : 0.f;
    rows[1][w] = src[h * 128 + w];
    rows[2][w] = (h < 127) ? src[(h + 1) * 128 + w] : 0.f;
    float wg[9];
    #pragma unroll
    for (int t = 0; t < 9; t++) wg[t] = __ldg(dww + o * 9 + t);
    __syncthreads();
    float acc = 0.f;
    #pragma unroll
    for (int dy = 0; dy < 3; dy++)
        #pragma unroll
        for (int dx = 0; dx < 3; dx++) {
            int ww = w + dx - 1;
            if (ww >= 0 && ww < 128)
                acc += wg[dy * 3 + dx] * rows[dy][ww];
        }
    d_qkvd[((long)(b * 576 + o)) * SP + h * 128 + w] = acc;
}

// ---------------- split-K Gram partials: per (slice,t,bh) a 48x48 block ----------------
// t=0: q · k^T ; t=1: cn · k^T
__global__ void __launch_bounds__(128) gram_kernel() {
    __shared__ unsigned Sa[32 * 56];
    __shared__ unsigned Sb[32 * 56];
    int slice = blockIdx.x;   // 0..7
    int t = blockIdx.y;       // 0..1
    int bh = blockIdx.z;      // 0..31
    int b = bh >> 2, h = bh & 3;
    const float* Arow = t ? (d_cnf + ((long)(b * 192 + h * 48)) * SP)
                          : (d_qkvd + ((long)(b * 576 + h * 48)) * SP);
    const float* Brow = d_qkvd + ((long)(b * 576 + 192 + h * 48)) * SP;
    int tid = threadIdx.x;
    int warp = tid >> 5, lane = tid & 31, g = lane >> 2, tg = lane & 3;
    float acc[6][4];
    #pragma unroll
    for (int i = 0; i < 6; i++)
        #pragma unroll
        for (int j = 0; j < 4; j++) acc[i][j] = 0.f;

    int kbase = slice * 2048;
    for (int kb = 0; kb < 2048; kb += 32) {
        __syncthreads();
        #pragma unroll
        for (int it = 0; it < 12; it++) {
            int idx = tid + it * 128;
            int m = idx >> 5, kk = idx & 31;
            Sa[kk * 56 + m] = f2tf(Arow[(long)m * SP + kbase + kb + kk]);
            Sb[kk * 56 + m] = f2tf(Brow[(long)m * SP + kbase + kb + kk]);
        }
        __syncthreads();
        if (warp < 3) {
            #pragma unroll
            for (int ks = 0; ks < 32; ks += 8) {
                unsigned a[4];
                int m = warp << 4;
                a[0] = Sa[(ks + tg) * 56 + m + g];
                a[1] = Sa[(ks + tg) * 56 + m + g + 8];
                a[2] = Sa[(ks + tg + 4) * 56 + m + g];
                a[3] = Sa[(ks + tg + 4) * 56 + m + g + 8];
                #pragma unroll
                for (int nt = 0; nt < 6; nt++) {
                    unsigned b0 = Sb[(ks + tg) * 56 + (nt << 3) + g];
                    unsigned b1 = Sb[(ks + tg + 4) * 56 + (nt << 3) + g];
                    mma8(acc[nt], a, b0, b1);
                }
            }
        }
    }
    if (warp < 3) {
        float* out = d_gramp + (((long)slice * 2 + t) * 32 + bh) * 2304;
        #pragma unroll
        for (int nt = 0; nt < 6; nt++) {
            int r = (warp << 4) + g;
            int col = (nt << 3) + (tg << 1);
            out[r * 48 + col] = acc[nt][0];
            out[r * 48 + col + 1] = acc[nt][1];
            out[(r + 8) * 48 + col] = acc[nt][2];
            out[(r + 8) * 48 + col + 1] = acc[nt][3];
        }
    }
}

// deterministic reduction of the 8 split-K slices
__global__ void gram_reduce_kernel() {
    int idx = blockIdx.x * 256 + threadIdx.x;
    if (idx < 2 * 32 * 2304) {
        float s = 0.f;
        #pragma unroll
        for (int p = 0; p < 8; p++) s += d_gramp[(long)p * (2 * 32 * 2304) + idx];
        d_gram[idx] = s;
    }
}

// ---------------- per-(b,c) norms + <q,cn> ----------------
__global__ void diag_kernel() {
    int bc = blockIdx.x;   // b*192 + c
    int b = bc / 192;
    const float* q = d_qkvd + ((long)(b * 576 + (bc - b * 192))) * SP;
    const float* k = q + 192L * SP;
    const float* cn = d_cnf + ((long)bc) * SP;
    float s0 = 0, s1 = 0, s2 = 0, s3 = 0;
    for (int i = threadIdx.x; i < SP; i += 256) {
        float qv = q[i], kv = k[i], cv = cn[i];
        s0 += qv * qv; s1 += kv * kv; s2 += cv * cv; s3 += qv * cv;
    }
    __shared__ float red[4][256];
    int tid = threadIdx.x;
    red[0][tid] = s0; red[1][tid] = s1; red[2][tid] = s2; red[3][tid] = s3;
    __syncthreads();
    for (int off = 128; off > 0; off >>= 1) {
        if (tid < off) {
            #pragma unroll
            for (int j = 0; j < 4; j++) red[j][tid] += red[j][tid + off];
        }
        __syncthreads();
    }
    if (tid < 4) d_normv[bc * 4 + tid] = red[tid][0];
}

// ---------------- logits + softmax -> attn ----------------
__global__ void attn_kernel(const float* __restrict__ temp) {
    int bh = blockIdx.x;
    int b = bh >> 2, h = bh & 3;
    __shared__ float L[48][49];
    __shared__ float qn[48], kn[48], cnn[48], un[48];
    int tid = threadIdx.x;
    if (tid < 48) {
        int bc = b * 192 + h * 48 + tid;
        float nq = d_normv[bc * 4 + 0];
        float nk = d_normv[bc * 4 + 1];
        float nc = d_normv[bc * 4 + 2];
        float dqc = d_normv[bc * 4 + 3];
        float q_n = fmaxf(sqrtf(nq), 1e-12f);
        float k_n = fmaxf(sqrtf(nk), 1e-12f);
        float c_n = fmaxf(sqrtf(nc), 1e-12f);
        float uu = 2.f + 2.f * dqc / (q_n * c_n);   // ||q_hat + cn_hat||^2
        float u_n = fmaxf(sqrtf(fmaxf(uu, 0.f)), 1e-12f);
        qn[tid] = q_n; kn[tid] = k_n; cnn[tid] = c_n; un[tid] = u_n;
    }
    __syncthreads();
    const float* Gqk = d_gram + (long)bh * 2304;
    const float* Gck = d_gram + (long)(32 + bh) * 2304;
    float tp = temp[h];
    for (int idx = tid; idx < 2304; idx += 256) {
        int c = idx / 48, d = idx - c * 48;
        L[c][d] = (Gqk[idx] / qn[c] + Gck[idx] / cnn[c]) / (un[c] * kn[d]) * tp;
    }
    __syncthreads();
    if (tid < 48) {
        float mx = -1e30f;
        #pragma unroll
        for (int d = 0; d < 48; d++) mx = fmaxf(mx, L[tid][d]);
        float e[48];
        float sum = 0.f;
        #pragma unroll
        for (int d = 0; d < 48; d++) { e[d] = expf(L[tid][d] - mx); sum += e[d]; }
        float inv = 1.f / sum;
        #pragma unroll
        for (int d = 0; d < 48; d++)
            d_attn[(long)bh * 2304 + tid * 48 + d] = e[d] * inv;
    }
}

// ---------------- M_b = P * blockdiag(attn_b)  (192x192 per batch) ----------------
__global__ void mker_kernel(const float* __restrict__ P) {
    int b = blockIdx.x;
    int idx = blockIdx.y * 256 + threadIdx.x;  // < 36864
    int o = idx / 192, j = idx - o * 192;
    int h = j / 48, d = j - h * 48;
    const float* att = d_attn + ((long)(b * 4 + h)) * 2304 + d;
    const float* pw = P + o * 192 + h * 48;
    float acc = 0.f;
    #pragma unroll
    for (int c2 = 0; c2 < 48; c2++) acc += pw[c2] * att[c2 * 48];
    d_Mmat[(long)b * 36864 + idx] = acc;
}

// ---------------- launch ----------------
extern "C" void kernel_launch(void* const* d_in, const int* in_sizes, int n_in,
                              void* d_out, int out_size) {
    const float* x     = (const float*)d_in[0];
    const float* cn    = (const float*)d_in[1];
    const float* w1    = (const float*)d_in[2];
    const float* w3    = (const float*)d_in[3];
    const float* qkvw  = (const float*)d_in[4];
    const float* dww   = (const float*)d_in[5];
    const float* projw = (const float*)d_in[6];
    const float* temp  = (const float*)d_in[7];
    float* out = (float*)d_out;

    float *pWc, *pCnf, *pQkv1, *pQkvd, *pM;
    cudaGetSymbolAddress((void**)&pWc, d_Wc);
    cudaGetSymbolAddress((void**)&pCnf, d_cnf);
    cudaGetSymbolAddress((void**)&pQkv1, d_qkv1);
    cudaGetSymbolAddress((void**)&pQkvd, d_qkvd);
    cudaGetSymbolAddress((void**)&pM, d_Mmat);

    compose_w_kernel<<<1728, 192>>>(w1, w3);
    pad_kernel<<<dim3(130, 192, 8), 130>>>(cn);
    // cn_f = composite 3x3 conv (implicit im2col GEMM), K = 192*9, M=192
    gemm_v2<1><<<dim3(128, 2, 8), 128>>>(pWc, (const float*)0, pCnf,
                                         1728, 0, 0, 192L * SP);
    // qkv1 = 1x1 conv, M=576 K=192
    gemm_v2<0><<<dim3(128, 6, 8), 128>>>(qkvw, x, pQkv1,
                                         192, 0, 192L * SP, 576L * SP);
    dw_kernel<<<dim3(128, 576, 8), 128>>>(dww);
    gram_kernel<<<dim3(8, 2, 32), 128>>>();
    gram_reduce_kernel<<<576, 256>>>();
    diag_kernel<<<1536, 256>>>();
    attn_kernel<<<32, 256>>>(temp);
    mker_kernel<<<dim3(8, 144), 256>>>(projw);
    // out = M_b @ v  (v = qkvd channels 384..575), M=192 K=192
    gemm_v2<0><<<dim3(128, 2, 8), 128>>>(pM, pQkvd + 384L * SP, out,
                                         192, 192L * 192, 576L * SP, 192L * SP);
}

// round 6
// speedup vs baseline: 1.3129x; 1.1066x over previous
#include <cuda_runtime.h>
#include <math.h>

#define SP 16384

// ---------------- scratch (device globals; every element rewritten per call) ----------------
__device__ float d_Wc[192 * 1728];                 // composite 3x3 cn weight, tap-major: [o][tap*192+ci]
__device__ float d_pad[8L * 192 * 130 * 132];      // zero-padded cn, row stride 132 (j=w+1)
__device__ float d_cnf[8L * 192 * SP];             // cn feature
__device__ float d_qkv1[8L * 576 * SP];            // qkv after 1x1
__device__ float d_qkvd[8L * 576 * SP];            // qkv after dw 3x3
__device__ float d_gramp[8L * 2 * 32 * 2304];      // split-K gram partials
__device__ float d_gram[2L * 32 * 2304];           // reduced grams (t=0:qk, t=1:ck)
__device__ float d_normv[8 * 192 * 4];             // per (b,c): |q|^2, |k|^2, |cn|^2, <q,cn>
__device__ float d_attn[32 * 2304];                // softmax attn per (b,h)
__device__ float d_Mmat[8 * 192 * 192];            // per-batch P * blockdiag(attn)

__device__ __forceinline__ unsigned f2tf(float f) {
    unsigned u;
    asm("cvt.rna.tf32.f32 %0, %1;" : "=r"(u) : "f"(f));
    return u;
}

__device__ __forceinline__ void mma8(float* acc, const unsigned* a, unsigned b0, unsigned b1) {
    asm volatile(
        "mma.sync.aligned.m16n8k8.row.col.f32.tf32.tf32.f32 "
        "{%0,%1,%2,%3}, {%4,%5,%6,%7}, {%8,%9}, {%0,%1,%2,%3};\n"
        : "+f"(acc[0]), "+f"(acc[1]), "+f"(acc[2]), "+f"(acc[3])
        : "r"(a[0]), "r"(a[1]), "r"(a[2]), "r"(a[3]), "r"(b0), "r"(b1));
}

__device__ __forceinline__ void cpa16(float* smem, const float* g) {
    unsigned d = (unsigned)__cvta_generic_to_shared(smem);
    asm volatile("cp.async.cg.shared.global [%0], [%1], 16;\n" :: "r"(d), "l"(g));
}

// ---------------- compose W'[o][tap*192+ci] = sum_m W3[o,m,tap]*W1[m,ci] (tap-major k) ------
__global__ void compose_w_kernel(const float* __restrict__ w1, const float* __restrict__ w3) {
    int o = blockIdx.x / 9, tap = blockIdx.x % 9;
    int ci = threadIdx.x;
    float acc = 0.f;
    for (int m = 0; m < 192; m++)
        acc += w3[(o * 192 + m) * 9 + tap] * w1[m * 192 + ci];
    d_Wc[o * 1728 + tap * 192 + ci] = acc;
}

// ---------------- zero-padded copy of cn: [b][c][130][132], j = w+1 ----------------
__global__ void pad_kernel(const float* __restrict__ cn) {
    int j = threadIdx.x;      // 0..131
    int hh = blockIdx.x;      // 0..129
    int c = blockIdx.y;
    int b = blockIdx.z;
    float v = 0.f;
    if (hh >= 1 && hh <= 128 && j >= 1 && j <= 128)
        v = cn[((long)(b * 192 + c)) * SP + (hh - 1) * 128 + (j - 1)];
    d_pad[(((long)(b * 192 + c)) * 130 + hh) * 132 + j] = v;
}

// ---------------- conv GEMM: cnf[m, s] = sum_k Wc[m,k] * im2col(pad)[k, s] ----------------
// K tap-major: tile of 16 k = 16 ci at ONE tap -> B loads are 16 aligned 132-float pad rows;
// dx shift applied at fragment read. Block 96(M) x 128(N=one image row), 128 thr, 4 warps.
__global__ void __launch_bounds__(128, 3) gemm_conv(
    const float* __restrict__ A, float* __restrict__ C)
{
    __shared__ float As[2][96 * 20];
    __shared__ float Bs[2][16 * 136];

    const int bz = blockIdx.z;
    const int h_row = blockIdx.x;        // spatial row 0..127
    const int n0 = h_row << 7;
    const int m0 = blockIdx.y * 96;
    const int tid = threadIdx.x;
    float* Cb = C + (long)bz * 192 * SP;

    const int ar = tid >> 2;             // 0..31
    const int akq = (tid & 3) << 2;
    const int warp = tid >> 5, lane = tid & 31;
    const int wm = (warp >> 1) * 48;
    const int wn = (warp & 1) << 6;
    const int g = lane >> 2, tg = lane & 3;

    float acc[3][8][4];
    #pragma unroll
    for (int i = 0; i < 3; i++)
        #pragma unroll
        for (int j = 0; j < 8; j++)
            #pragma unroll
            for (int l = 0; l < 4; l++) acc[i][j][l] = 0.f;

    auto issue = [&](int t, int buf) {
        int k0 = t << 4;
        int tap = t / 12;                 // k0/192
        int ci0 = k0 - tap * 192;
        int dy = tap / 3;
        #pragma unroll
        for (int i = 0; i < 3; i++) {
            int r = ar + (i << 5);
            cpa16(&As[buf][r * 20 + akq], A + (long)(m0 + r) * 1728 + k0 + akq);
        }
        const float* base = d_pad + (((long)(bz * 192 + ci0)) * 130 + h_row + dy) * 132;
        #pragma unroll
        for (int it = 0; it < 5; it++) {
            int idx = tid + (it << 7);
            if (idx < 528) {
                int kr = idx / 33;
                int q = (idx - kr * 33) << 2;
                cpa16(&Bs[buf][kr * 136 + q], base + (long)kr * (130 * 132) + q);
            }
        }
        asm volatile("cp.async.commit_group;\n");
    };

    auto compute = [&](int buf, int dx) {
        #pragma unroll
        for (int ks = 0; ks < 16; ks += 8) {
            unsigned af[3][4];
            #pragma unroll
            for (int mt = 0; mt < 3; mt++) {
                int m = wm + (mt << 4);
                af[mt][0] = f2tf(As[buf][(m + g) * 20 + ks + tg]);
                af[mt][1] = f2tf(As[buf][(m + g + 8) * 20 + ks + tg]);
                af[mt][2] = f2tf(As[buf][(m + g) * 20 + ks + tg + 4]);
                af[mt][3] = f2tf(As[buf][(m + g + 8) * 20 + ks + tg + 4]);
            }
            #pragma unroll
            for (int nt = 0; nt < 8; nt++) {
                int n = wn + (nt << 3) + g + dx;
                unsigned b0 = f2tf(Bs[buf][(ks + tg) * 136 + n]);
                unsigned b1 = f2tf(Bs[buf][(ks + tg + 4) * 136 + n]);
                #pragma unroll
                for (int mt = 0; mt < 3; mt++)
                    mma8(acc[mt][nt], af[mt], b0, b1);
            }
        }
    };

    issue(0, 0);
    for (int t = 0; t < 108; t++) {
        asm volatile("cp.async.wait_group 0;\n");
        __syncthreads();
        if (t + 1 < 108) issue(t + 1, (t + 1) & 1);
        compute(t & 1, (t / 12) % 3);
    }

    #pragma unroll
    for (int mt = 0; mt < 3; mt++)
        #pragma unroll
        for (int nt = 0; nt < 8; nt++) {
            long row = m0 + wm + (mt << 4) + g;
            int col = n0 + wn + (nt << 3) + (tg << 1);
            *reinterpret_cast<float2*>(Cb + row * SP + col) =
                make_float2(acc[mt][nt][0], acc[mt][nt][1]);
            *reinterpret_cast<float2*>(Cb + (row + 8) * SP + col) =
                make_float2(acc[mt][nt][2], acc[mt][nt][3]);
        }
}

// ---------------- dense tf32 GEMM v3: block 64(M) x 256(N) x 16(K), 256 thr, 8 warps -------
// warp tile 32x64 (mt=2, nt=8); 2 CTAs/SM (25% occ); N=256 halves A L2 re-reads.
__global__ void __launch_bounds__(256, 2) gemm_v3(
    const float* __restrict__ A, const float* __restrict__ B, float* __restrict__ C,
    int K, long sA, long sB, long sC)
{
    __shared__ float As[2][64 * 20];
    __shared__ float Bs[2][16 * 264];

    const int bz = blockIdx.z;
    const int n0 = blockIdx.x << 8;
    const int m0 = blockIdx.y << 6;
    const int tid = threadIdx.x;
    const float* Ab = A + (long)bz * sA;
    const float* Bb = B + (long)bz * sB;
    float* Cb = C + (long)bz * sC;

    const int ar = tid >> 2;            // 0..63
    const int akq = (tid & 3) << 2;
    const int bkr = tid >> 4;           // 0..15
    const int bnq = (tid & 15) << 4;    // 0..240
    const int warp = tid >> 5, lane = tid & 31;
    const int wm = (warp >> 2) << 5;    // 0,32
    const int wn = (warp & 3) << 6;     // 0,64,128,192
    const int g = lane >> 2, tg = lane & 3;

    float acc[2][8][4];
    #pragma unroll
    for (int i = 0; i < 2; i++)
        #pragma unroll
        for (int j = 0; j < 8; j++)
            #pragma unroll
            for (int l = 0; l < 4; l++) acc[i][j][l] = 0.f;

    auto issue = [&](int t, int buf) {
        int k0 = t << 4;
        cpa16(&As[buf][ar * 20 + akq], Ab + (long)(m0 + ar) * K + k0 + akq);
        const float* p = Bb + (long)(k0 + bkr) * SP + n0 + bnq;
        #pragma unroll
        for (int j = 0; j < 4; j++)
            cpa16(&Bs[buf][bkr * 264 + bnq + (j << 2)], p + (j << 2));
        asm volatile("cp.async.commit_group;\n");
    };

    auto compute = [&](int buf) {
        #pragma unroll
        for (int ks = 0; ks < 16; ks += 8) {
            unsigned af[2][4];
            #pragma unroll
            for (int mt = 0; mt < 2; mt++) {
                int m = wm + (mt << 4);
                af[mt][0] = f2tf(As[buf][(m + g) * 20 + ks + tg]);
                af[mt][1] = f2tf(As[buf][(m + g + 8) * 20 + ks + tg]);
                af[mt][2] = f2tf(As[buf][(m + g) * 20 + ks + tg + 4]);
                af[mt][3] = f2tf(As[buf][(m + g + 8) * 20 + ks + tg + 4]);
            }
            #pragma unroll
            for (int nt = 0; nt < 8; nt++) {
                int n = wn + (nt << 3) + g;
                unsigned b0 = f2tf(Bs[buf][(ks + tg) * 264 + n]);
                unsigned b1 = f2tf(Bs[buf][(ks + tg + 4) * 264 + n]);
                #pragma unroll
                for (int mt = 0; mt < 2; mt++)
                    mma8(acc[mt][nt], af[mt], b0, b1);
            }
        }
    };

    const int T = K >> 4;
    issue(0, 0);
    for (int t = 0; t < T; t++) {
        asm volatile("cp.async.wait_group 0;\n");
        __syncthreads();
        if (t + 1 < T) issue(t + 1, (t + 1) & 1);
        compute(t & 1);
    }

    #pragma unroll
    for (int mt = 0; mt < 2; mt++)
        #pragma unroll
        for (int nt = 0; nt < 8; nt++) {
            long row = m0 + wm + (mt << 4) + g;
            int col = n0 + wn + (nt << 3) + (tg << 1);
            *reinterpret_cast<float2*>(Cb + row * SP + col) =
                make_float2(acc[mt][nt][0], acc[mt][nt][1]);
            *reinterpret_cast<float2*>(Cb + (row + 8) * SP + col) =
                make_float2(acc[mt][nt][2], acc[mt][nt][3]);
        }
}

// ---------------- depthwise 3x3 (SAME, zero pad) on qkv1 -> qkvd ----------------
__global__ void dw_kernel(const float* __restrict__ dww) {
    __shared__ float rows[3][128];
    int w = threadIdx.x;
    int h = blockIdx.x;
    int o = blockIdx.y;
    int b = blockIdx.z;
    const float* src = d_qkv1 + ((long)(b * 576 + o)) * SP;
    rows[0][w] = (h > 0) ? src[(h - 1) * 128 + w] : 0.f;
    rows[1][w] = src[h * 128 + w];
    rows[2][w] = (h < 127) ? src[(h + 1) * 128 + w] : 0.f;
    float wg[9];
    #pragma unroll
    for (int t = 0; t < 9; t++) wg[t] = __ldg(dww + o * 9 + t);
    __syncthreads();
    float acc = 0.f;
    #pragma unroll
    for (int dy = 0; dy < 3; dy++)
        #pragma unroll
        for (int dx = 0; dx < 3; dx++) {
            int ww = w + dx - 1;
            if (ww >= 0 && ww < 128)
                acc += wg[dy * 3 + dx] * rows[dy][ww];
        }
    d_qkvd[((long)(b * 576 + o)) * SP + h * 128 + w] = acc;
}

// ---------------- split-K Gram partials: per (slice,t,bh) a 48x48 block ----------------
__global__ void __launch_bounds__(128) gram_kernel() {
    __shared__ unsigned Sa[32 * 56];
    __shared__ unsigned Sb[32 * 56];
    int slice = blockIdx.x;   // 0..7
    int t = blockIdx.y;       // 0..1
    int bh = blockIdx.z;      // 0..31
    int b = bh >> 2, h = bh & 3;
    const float* Arow = t ? (d_cnf + ((long)(b * 192 + h * 48)) * SP)
                          : (d_qkvd + ((long)(b * 576 + h * 48)) * SP);
    const float* Brow = d_qkvd + ((long)(b * 576 + 192 + h * 48)) * SP;
    int tid = threadIdx.x;
    int warp = tid >> 5, lane = tid & 31, g = lane >> 2, tg = lane & 3;
    float acc[6][4];
    #pragma unroll
    for (int i = 0; i < 6; i++)
        #pragma unroll
        for (int j = 0; j < 4; j++) acc[i][j] = 0.f;

    int kbase = slice * 2048;
    for (int kb = 0; kb < 2048; kb += 32) {
        __syncthreads();
        #pragma unroll
        for (int it = 0; it < 12; it++) {
            int idx = tid + it * 128;
            int m = idx >> 5, kk = idx & 31;
            Sa[kk * 56 + m] = f2tf(Arow[(long)m * SP + kbase + kb + kk]);
            Sb[kk * 56 + m] = f2tf(Brow[(long)m * SP + kbase + kb + kk]);
        }
        __syncthreads();
        if (warp < 3) {
            #pragma unroll
            for (int ks = 0; ks < 32; ks += 8) {
                unsigned a[4];
                int m = warp << 4;
                a[0] = Sa[(ks + tg) * 56 + m + g];
                a[1] = Sa[(ks + tg) * 56 + m + g + 8];
                a[2] = Sa[(ks + tg + 4) * 56 + m + g];
                a[3] = Sa[(ks + tg + 4) * 56 + m + g + 8];
                #pragma unroll
                for (int nt = 0; nt < 6; nt++) {
                    unsigned b0 = Sb[(ks + tg) * 56 + (nt << 3) + g];
                    unsigned b1 = Sb[(ks + tg + 4) * 56 + (nt << 3) + g];
                    mma8(acc[nt], a, b0, b1);
                }
            }
        }
    }
    if (warp < 3) {
        float* out = d_gramp + (((long)slice * 2 + t) * 32 + bh) * 2304;
        #pragma unroll
        for (int nt = 0; nt < 6; nt++) {
            int r = (warp << 4) + g;
            int col = (nt << 3) + (tg << 1);
            out[r * 48 + col] = acc[nt][0];
            out[r * 48 + col + 1] = acc[nt][1];
            out[(r + 8) * 48 + col] = acc[nt][2];
            out[(r + 8) * 48 + col + 1] = acc[nt][3];
        }
    }
}

// deterministic reduction of the 8 split-K slices
__global__ void gram_reduce_kernel() {
    int idx = blockIdx.x * 256 + threadIdx.x;
    if (idx < 2 * 32 * 2304) {
        float s = 0.f;
        #pragma unroll
        for (int p = 0; p < 8; p++) s += d_gramp[(long)p * (2 * 32 * 2304) + idx];
        d_gram[idx] = s;
    }
}

// ---------------- per-(b,c) norms + <q,cn> ----------------
__global__ void diag_kernel() {
    int bc = blockIdx.x;   // b*192 + c
    int b = bc / 192;
    const float* q = d_qkvd + ((long)(b * 576 + (bc - b * 192))) * SP;
    const float* k = q + 192L * SP;
    const float* cn = d_cnf + ((long)bc) * SP;
    float s0 = 0, s1 = 0, s2 = 0, s3 = 0;
    for (int i = threadIdx.x; i < SP; i += 256) {
        float qv = q[i], kv = k[i], cv = cn[i];
        s0 += qv * qv; s1 += kv * kv; s2 += cv * cv; s3 += qv * cv;
    }
    __shared__ float red[4][256];
    int tid = threadIdx.x;
    red[0][tid] = s0; red[1][tid] = s1; red[2][tid] = s2; red[3][tid] = s3;
    __syncthreads();
    for (int off = 128; off > 0; off >>= 1) {
        if (tid < off) {
            #pragma unroll
            for (int j = 0; j < 4; j++) red[j][tid] += red[j][tid + off];
        }
        __syncthreads();
    }
    if (tid < 4) d_normv[bc * 4 + tid] = red[tid][0];
}

// ---------------- logits + softmax -> attn ----------------
__global__ void attn_kernel(const float* __restrict__ temp) {
    int bh = blockIdx.x;
    int b = bh >> 2, h = bh & 3;
    __shared__ float L[48][49];
    __shared__ float qn[48], kn[48], cnn[48], un[48];
    int tid = threadIdx.x;
    if (tid < 48) {
        int bc = b * 192 + h * 48 + tid;
        float nq = d_normv[bc * 4 + 0];
        float nk = d_normv[bc * 4 + 1];
        float nc = d_normv[bc * 4 + 2];
        float dqc = d_normv[bc * 4 + 3];
        float q_n = fmaxf(sqrtf(nq), 1e-12f);
        float k_n = fmaxf(sqrtf(nk), 1e-12f);
        float c_n = fmaxf(sqrtf(nc), 1e-12f);
        float uu = 2.f + 2.f * dqc / (q_n * c_n);   // ||q_hat + cn_hat||^2
        float u_n = fmaxf(sqrtf(fmaxf(uu, 0.f)), 1e-12f);
        qn[tid] = q_n; kn[tid] = k_n; cnn[tid] = c_n; un[tid] = u_n;
    }
    __syncthreads();
    const float* Gqk = d_gram + (long)bh * 2304;
    const float* Gck = d_gram + (long)(32 + bh) * 2304;
    float tp = temp[h];
    for (int idx = tid; idx < 2304; idx += 256) {
        int c = idx / 48, d = idx - c * 48;
        L[c][d] = (Gqk[idx] / qn[c] + Gck[idx] / cnn[c]) / (un[c] * kn[d]) * tp;
    }
    __syncthreads();
    if (tid < 48) {
        float mx = -1e30f;
        #pragma unroll
        for (int d = 0; d < 48; d++) mx = fmaxf(mx, L[tid][d]);
        float e[48];
        float sum = 0.f;
        #pragma unroll
        for (int d = 0; d < 48; d++) { e[d] = expf(L[tid][d] - mx); sum += e[d]; }
        float inv = 1.f / sum;
        #pragma unroll
        for (int d = 0; d < 48; d++)
            d_attn[(long)bh * 2304 + tid * 48 + d] = e[d] * inv;
    }
}

// ---------------- M_b = P * blockdiag(attn_b)  (192x192 per batch) ----------------
__global__ void mker_kernel(const float* __restrict__ P) {
    int b = blockIdx.x;
    int idx = blockIdx.y * 256 + threadIdx.x;  // < 36864
    int o = idx / 192, j = idx - o * 192;
    int h = j / 48, d = j - h * 48;
    const float* att = d_attn + ((long)(b * 4 + h)) * 2304 + d;
    const float* pw = P + o * 192 + h * 48;
    float acc = 0.f;
    #pragma unroll
    for (int c2 = 0; c2 < 48; c2++) acc += pw[c2] * att[c2 * 48];
    d_Mmat[(long)b * 36864 + idx] = acc;
}

// ---------------- launch ----------------
extern "C" void kernel_launch(void* const* d_in, const int* in_sizes, int n_in,
                              void* d_out, int out_size) {
    const float* x     = (const float*)d_in[0];
    const float* cn    = (const float*)d_in[1];
    const float* w1    = (const float*)d_in[2];
    const float* w3    = (const float*)d_in[3];
    const float* qkvw  = (const float*)d_in[4];
    const float* dww   = (const float*)d_in[5];
    const float* projw = (const float*)d_in[6];
    const float* temp  = (const float*)d_in[7];
    float* out = (float*)d_out;

    float *pWc, *pCnf, *pQkv1, *pQkvd, *pM;
    cudaGetSymbolAddress((void**)&pWc, d_Wc);
    cudaGetSymbolAddress((void**)&pCnf, d_cnf);
    cudaGetSymbolAddress((void**)&pQkv1, d_qkv1);
    cudaGetSymbolAddress((void**)&pQkvd, d_qkvd);
    cudaGetSymbolAddress((void**)&pM, d_Mmat);

    compose_w_kernel<<<1728, 192>>>(w1, w3);
    pad_kernel<<<dim3(130, 192, 8), 132>>>(cn);
    // cn_f = composite 3x3 conv (tap-major implicit im2col GEMM), K=1728, M=192
    gemm_conv<<<dim3(128, 2, 8), 128>>>(pWc, pCnf);
    // qkv1 = 1x1 conv, M=576 K=192
    gemm_v3<<<dim3(64, 9, 8), 256>>>(qkvw, x, pQkv1,
                                     192, 0, 192L * SP, 576L * SP);
    dw_kernel<<<dim3(128, 576, 8), 128>>>(dww);
    gram_kernel<<<dim3(8, 2, 32), 128>>>();
    gram_reduce_kernel<<<576, 256>>>();
    diag_kernel<<<1536, 256>>>();
    attn_kernel<<<32, 256>>>(temp);
    mker_kernel<<<dim3(8, 144), 256>>>(projw);
    // out = M_b @ v  (v = qkvd channels 384..575), M=192 K=192
    gemm_v3<<<dim3(64, 3, 8), 256>>>(pM, pQkvd + 384L * SP, out,
                                     192, 192L * 192, 576L * SP, 192L * SP);
}

// round 8
// speedup vs baseline: 1.6486x; 1.2557x over previous
#include <cuda_runtime.h>
#include <math.h>

#define SP 16384

// ---------------- scratch (device globals; every element rewritten per call) ----------------
__device__ float4 d_WcF[2592 * 32];                // composite conv weight, fragment order, tf32-rounded
__device__ float4 d_WqkvF[36 * 24 * 32];           // qkv weight, fragment order, tf32-rounded
__device__ float4 d_MmatF[8 * 12 * 24 * 32];       // per-batch P*blockdiag(attn), fragment order
__device__ float d_pad[8L * 192 * 130 * 132];      // zero-padded cn, tf32-rounded, row stride 132 (j=w+1)
__device__ float d_cnf[8L * 192 * SP];             // cn feature
__device__ float d_qkv1[8L * 576 * SP];            // qkv after 1x1
__device__ float d_qkvd[8L * 576 * SP];            // qkv after dw 3x3
__device__ float d_gramp[8L * 2 * 32 * 2304];      // split-K gram partials
__device__ float d_gram[2L * 32 * 2304];           // reduced grams (t=0:qk, t=1:ck)
__device__ float d_normv[8 * 192 * 4];             // per (b,c): |q|^2, |k|^2, |cn|^2, <q,cn>
__device__ float d_attn[32 * 2304];                // softmax attn per (b,h)

__device__ __forceinline__ unsigned f2tf(float f) {
    unsigned u;
    asm("cvt.rna.tf32.f32 %0, %1;" : "=r"(u) : "f"(f));
    return u;
}
__device__ __forceinline__ float f2tff(float f) { return __uint_as_float(f2tf(f)); }

__device__ __forceinline__ void mma8(float* acc, const unsigned* a, unsigned b0, unsigned b1) {
    asm volatile(
        "mma.sync.aligned.m16n8k8.row.col.f32.tf32.tf32.f32 "
        "{%0,%1,%2,%3}, {%4,%5,%6,%7}, {%8,%9}, {%0,%1,%2,%3};\n"
        : "+f"(acc[0]), "+f"(acc[1]), "+f"(acc[2]), "+f"(acc[3])
        : "r"(a[0]), "r"(a[1]), "r"(a[2]), "r"(a[3]), "r"(b0), "r"(b1));
}

__device__ __forceinline__ void cpa16(float* smem, const float* g) {
    unsigned d = (unsigned)__cvta_generic_to_shared(smem);
    asm volatile("cp.async.cg.shared.global [%0], [%1], 16;\n" :: "r"(d), "l"(g));
}

// ---------------- composite conv weight, fragment order ----------------
// cell = (((mb*3+dy)*12+cib)*3+dx)*2+ks8 ; lane gives (g,tg).
// value(o,ci) = sum_m W3[o,m,tap]*W1[m,ci], tap = dy*3+dx.
__global__ void compose_w_frag(const float* __restrict__ w1, const float* __restrict__ w3) {
    int cell = blockIdx.x;
    int lane = threadIdx.x;
    int ks8 = cell & 1;
    int c2 = cell >> 1;
    int dx = c2 % 3;  int c3 = c2 / 3;
    int cib = c3 % 12; int c4 = c3 / 12;
    int dy = c4 % 3;  int mb = c4 / 3;
    int g = lane >> 2, tg = lane & 3;
    int tap = dy * 3 + dx;
    int o0 = mb * 16 + g;
    int ci0 = cib * 16 + ks8 * 8 + tg;
    float s0 = 0, s1 = 0, s2 = 0, s3 = 0;
    for (int m = 0; m < 192; m++) {
        float a0 = w3[(o0 * 192 + m) * 9 + tap];
        float a1 = w3[((o0 + 8) * 192 + m) * 9 + tap];
        float b0 = w1[m * 192 + ci0];
        float b1 = w1[m * 192 + ci0 + 4];
        s0 += a0 * b0; s1 += a1 * b0; s2 += a0 * b1; s3 += a1 * b1;
    }
    d_WcF[cell * 32 + lane] = make_float4(f2tff(s0), f2tff(s1), f2tff(s2), f2tff(s3));
}

// ---------------- qkv weight fragment swizzle ----------------
__global__ void swz_qkvw(const float* __restrict__ w) {
    int mb = blockIdx.x / 24, kb8 = blockIdx.x % 24;
    int lane = threadIdx.x;
    int g = lane >> 2, tg = lane & 3;
    int o0 = mb * 16 + g, k0 = kb8 * 8 + tg;
    float4 v;
    v.x = f2tff(w[o0 * 192 + k0]);
    v.y = f2tff(w[(o0 + 8) * 192 + k0]);
    v.z = f2tff(w[o0 * 192 + k0 + 4]);
    v.w = f2tff(w[(o0 + 8) * 192 + k0 + 4]);
    d_WqkvF[(mb * 24 + kb8) * 32 + lane] = v;
}

// ---------------- zero-padded tf32-rounded copy of cn: [b][c][130][132], j = w+1 -----------
__global__ void pad_kernel(const float* __restrict__ cn) {
    int j = threadIdx.x;      // 0..131
    int hh = blockIdx.x;      // 0..129
    int c = blockIdx.y;
    int b = blockIdx.z;
    float v = 0.f;
    if (hh >= 1 && hh <= 128 && j >= 1 && j <= 128)
        v = f2tff(cn[((long)(b * 192 + c)) * SP + (hh - 1) * 128 + (j - 1)]);
    d_pad[(((long)(b * 192 + c)) * 130 + hh) * 132 + j] = v;
}

// ---------------- conv GEMM v2: 36 K-groups of (dy, ci-block); one B tile serves 3 dx ------
// Block 96(M) x 128(N=one image row), 128 thr, 4 warps, warp tile 48x64.
// A fragments direct from d_WcF (LDG.128, pre-tf32). B pre-rounded in d_pad -> no CVT at all.
__global__ void __launch_bounds__(128, 3) gemm_conv2(float* __restrict__ C)
{
    __shared__ float Bs[2][16 * 136];

    const int bz = blockIdx.z;
    const int h_row = blockIdx.x;        // spatial row 0..127
    const int n0 = h_row << 7;
    const int m0 = blockIdx.y * 96;
    const int mb0 = blockIdx.y * 6;
    const int tid = threadIdx.x;
    float* Cb = C + (long)bz * 192 * SP;

    const int warp = tid >> 5, lane = tid & 31;
    const int wm = (warp >> 1) * 48;
    const int wn = (warp & 1) << 6;
    const int g = lane >> 2, tg = lane & 3;
    const int mwb = (warp >> 1) * 3;     // first 16-row block of this warp

    float acc[3][8][4];
    #pragma unroll
    for (int i = 0; i < 3; i++)
        #pragma unroll
        for (int j = 0; j < 8; j++)
            #pragma unroll
            for (int l = 0; l < 4; l++) acc[i][j][l] = 0.f;

    auto issueB = [&](int gg, int buf) {
        int dy = gg / 12;
        int ci0 = (gg - dy * 12) << 4;
        const float* base = d_pad + (((long)(bz * 192 + ci0)) * 130 + h_row + dy) * 132;
        #pragma unroll
        for (int it = 0; it < 5; it++) {
            int idx = tid + (it << 7);
            if (idx < 528) {
                int kr = idx / 33;
                int q = (idx - kr * 33) << 2;
                cpa16(&Bs[buf][kr * 136 + q], base + (long)kr * (130 * 132) + q);
            }
        }
        asm volatile("cp.async.commit_group;\n");
    };

    auto pass = [&](int buf, int dy, int cib, int dx) {
        #pragma unroll
        for (int ks8 = 0; ks8 < 2; ks8++) {
            unsigned af[3][4];
            #pragma unroll
            for (int mt = 0; mt < 3; mt++) {
                int cell = ((((mb0 + mwb + mt) * 3 + dy) * 12 + cib) * 3 + dx) * 2 + ks8;
                float4 a = d_WcF[cell * 32 + lane];
                af[mt][0] = __float_as_uint(a.x);
                af[mt][1] = __float_as_uint(a.y);
                af[mt][2] = __float_as_uint(a.z);
                af[mt][3] = __float_as_uint(a.w);
            }
            int kr = ks8 << 3;
            #pragma unroll
            for (int nt = 0; nt < 8; nt++) {
                int n = wn + (nt << 3) + g + dx;
                unsigned b0 = __float_as_uint(Bs[buf][(kr + tg) * 136 + n]);
                unsigned b1 = __float_as_uint(Bs[buf][(kr + tg + 4) * 136 + n]);
                #pragma unroll
                for (int mt = 0; mt < 3; mt++)
                    mma8(acc[mt][nt], af[mt], b0, b1);
            }
        }
    };

    issueB(0, 0);
    for (int gg = 0; gg < 36; gg++) {
        asm volatile("cp.async.wait_group 0;\n");
        __syncthreads();
        if (gg + 1 < 36) issueB(gg + 1, (gg + 1) & 1);
        int dy = gg / 12;
        int cib = gg - dy * 12;
        pass(gg & 1, dy, cib, 0);
        pass(gg & 1, dy, cib, 1);
        pass(gg & 1, dy, cib, 2);
        __syncthreads();
    }

    #pragma unroll
    for (int mt = 0; mt < 3; mt++)
        #pragma unroll
        for (int nt = 0; nt < 8; nt++) {
            long row = m0 + wm + (mt << 4) + g;
            int col = n0 + wn + (nt << 3) + (tg << 1);
            *reinterpret_cast<float2*>(Cb + row * SP + col) =
                make_float2(acc[mt][nt][0], acc[mt][nt][1]);
            *reinterpret_cast<float2*>(Cb + (row + 8) * SP + col) =
                make_float2(acc[mt][nt][2], acc[mt][nt][3]);
        }
}

// ---------------- dense tf32 GEMM v4: A-frag direct LDG, B via cp.async smem ----------------
// Block 96(M) x 128(N) x 16(K), 128 thr, 4 warps, warp tile 48x64 (v2 geometry, proven).
__global__ void __launch_bounds__(128, 3) gemm_v4(
    const float4* __restrict__ Af, const float* __restrict__ B, float* __restrict__ C,
    int KB8, long sAf, long sB, long sC)
{
    __shared__ float Bs[2][16 * 136];

    const int bz = blockIdx.z;
    const int n0 = blockIdx.x << 7;
    const int m0 = blockIdx.y * 96;
    const int mb0 = blockIdx.y * 6;
    const int tid = threadIdx.x;
    const float4* Ab = Af + (long)bz * sAf;
    const float* Bb = B + (long)bz * sB;
    float* Cb = C + (long)bz * sC;

    const int bk = tid >> 4;            // 0..7
    const int bn = (tid & 15) << 3;     // 0..120
    const int warp = tid >> 5, lane = tid & 31;
    const int wm = (warp >> 1) * 48;
    const int wn = (warp & 1) << 6;
    const int g = lane >> 2, tg = lane & 3;
    const int mwb = (warp >> 1) * 3;

    float acc[3][8][4];
    #pragma unroll
    for (int i = 0; i < 3; i++)
        #pragma unroll
        for (int j = 0; j < 8; j++)
            #pragma unroll
            for (int l = 0; l < 4; l++) acc[i][j][l] = 0.f;

    auto issue = [&](int t, int buf) {
        int k0 = t << 4;
        #pragma unroll
        for (int i = 0; i < 2; i++) {
            int kr = bk + (i << 3);
            const float* p = Bb + (long)(k0 + kr) * SP + n0 + bn;
            cpa16(&Bs[buf][kr * 136 + bn], p);
            cpa16(&Bs[buf][kr * 136 + bn + 4], p + 4);
        }
        asm volatile("cp.async.commit_group;\n");
    };

    auto compute = [&](int buf, int t) {
        #pragma unroll
        for (int ks8 = 0; ks8 < 2; ks8++) {
            int kb8 = (t << 1) + ks8;
            unsigned af[3][4];
            #pragma unroll
            for (int mt = 0; mt < 3; mt++) {
                float4 a = Ab[((mb0 + mwb + mt) * KB8 + kb8) * 32 + lane];
                af[mt][0] = __float_as_uint(a.x);
                af[mt][1] = __float_as_uint(a.y);
                af[mt][2] = __float_as_uint(a.z);
                af[mt][3] = __float_as_uint(a.w);
            }
            int kr = ks8 << 3;
            #pragma unroll
            for (int nt = 0; nt < 8; nt++) {
                int n = wn + (nt << 3) + g;
                unsigned b0 = f2tf(Bs[buf][(kr + tg) * 136 + n]);
                unsigned b1 = f2tf(Bs[buf][(kr + tg + 4) * 136 + n]);
                #pragma unroll
                for (int mt = 0; mt < 3; mt++)
                    mma8(acc[mt][nt], af[mt], b0, b1);
            }
        }
    };

    const int T = KB8 >> 1;
    issue(0, 0);
    for (int t = 0; t < T; t++) {
        asm volatile("cp.async.wait_group 0;\n");
        __syncthreads();
        if (t + 1 < T) issue(t + 1, (t + 1) & 1);
        compute(t & 1, t);
        __syncthreads();
    }

    #pragma unroll
    for (int mt = 0; mt < 3; mt++)
        #pragma unroll
        for (int nt = 0; nt < 8; nt++) {
            long row = m0 + wm + (mt << 4) + g;
            int col = n0 + wn + (nt << 3) + (tg << 1);
            *reinterpret_cast<float2*>(Cb + row * SP + col) =
                make_float2(acc[mt][nt][0], acc[mt][nt][1]);
            *reinterpret_cast<float2*>(Cb + (row + 8) * SP + col) =
                make_float2(acc[mt][nt][2], acc[mt][nt][3]);
        }
}

// ---------------- depthwise 3x3: one CTA per (b, channel), streams rows via 5-slot ring ----
__global__ void dw_v2(const float* __restrict__ dww) {
    __shared__ float ring[5][128];
    int w = threadIdx.x;
    int o = blockIdx.x;
    int b = blockIdx.y;
    const float* src = d_qkv1 + ((long)(b * 576 + o)) * SP;
    float* dst = d_qkvd + ((long)(b * 576 + o)) * SP;
    float wg[9];
    #pragma unroll
    for (int t = 0; t < 9; t++) wg[t] = __ldg(dww + o * 9 + t);
    ring[0][w] = src[w];
    ring[1][w] = src[128 + w];
    __syncthreads();
    for (int h = 0; h < 128; h++) {
        if (h + 2 < 128) ring[(h + 2) % 5][w] = src[(h + 2) * 128 + w];
        __syncthreads();
        const float* r0 = ring[(h + 4) % 5];   // row h-1 (slot (h-1)%5)
        const float* r1 = ring[h % 5];
        const float* r2 = ring[(h + 1) % 5];
        float acc = 0.f;
        if (h > 0) {
            if (w > 0)   acc += wg[0] * r0[w - 1];
                         acc += wg[1] * r0[w];
            if (w < 127) acc += wg[2] * r0[w + 1];
        }
        if (w > 0)   acc += wg[3] * r1[w - 1];
                     acc += wg[4] * r1[w];
        if (w < 127) acc += wg[5] * r1[w + 1];
        if (h < 127) {
            if (w > 0)   acc += wg[6] * r2[w - 1];
                         acc += wg[7] * r2[w];
            if (w < 127) acc += wg[8] * r2[w + 1];
        }
        dst[h * 128 + w] = acc;
        __syncthreads();
    }
}

// ---------------- split-K Gram partials: per (slice,t,bh) a 48x48 block ----------------
__global__ void __launch_bounds__(128) gram_kernel() {
    __shared__ unsigned Sa[32 * 56];
    __shared__ unsigned Sb[32 * 56];
    int slice = blockIdx.x;   // 0..7
    int t = blockIdx.y;       // 0..1
    int bh = blockIdx.z;      // 0..31
    int b = bh >> 2, h = bh & 3;
    const float* Arow = t ? (d_cnf + ((long)(b * 192 + h * 48)) * SP)
                          : (d_qkvd + ((long)(b * 576 + h * 48)) * SP);
    const float* Brow = d_qkvd + ((long)(b * 576 + 192 + h * 48)) * SP;
    int tid = threadIdx.x;
    int warp = tid >> 5, lane = tid & 31, g = lane >> 2, tg = lane & 3;
    float acc[6][4];
    #pragma unroll
    for (int i = 0; i < 6; i++)
        #pragma unroll
        for (int j = 0; j < 4; j++) acc[i][j] = 0.f;

    int kbase = slice * 2048;
    for (int kb = 0; kb < 2048; kb += 32) {
        __syncthreads();
        #pragma unroll
        for (int it = 0; it < 12; it++) {
            int idx = tid + it * 128;
            int m = idx >> 5, kk = idx & 31;
            Sa[kk * 56 + m] = f2tf(Arow[(long)m * SP + kbase + kb + kk]);
            Sb[kk * 56 + m] = f2tf(Brow[(long)m * SP + kbase + kb + kk]);
        }
        __syncthreads();
        if (warp < 3) {
            #pragma unroll
            for (int ks = 0; ks < 32; ks += 8) {
                unsigned a[4];
                int m = warp << 4;
                a[0] = Sa[(ks + tg) * 56 + m + g];
                a[1] = Sa[(ks + tg) * 56 + m + g + 8];
                a[2] = Sa[(ks + tg + 4) * 56 + m + g];
                a[3] = Sa[(ks + tg + 4) * 56 + m + g + 8];
                #pragma unroll
                for (int nt = 0; nt < 6; nt++) {
                    unsigned b0 = Sb[(ks + tg) * 56 + (nt << 3) + g];
                    unsigned b1 = Sb[(ks + tg + 4) * 56 + (nt << 3) + g];
                    mma8(acc[nt], a, b0, b1);
                }
            }
        }
    }
    if (warp < 3) {
        float* out = d_gramp + (((long)slice * 2 + t) * 32 + bh) * 2304;
        #pragma unroll
        for (int nt = 0; nt < 6; nt++) {
            int r = (warp << 4) + g;
            int col = (nt << 3) + (tg << 1);
            out[r * 48 + col] = acc[nt][0];
            out[r * 48 + col + 1] = acc[nt][1];
            out[(r + 8) * 48 + col] = acc[nt][2];
            out[(r + 8) * 48 + col + 1] = acc[nt][3];
        }
    }
}

// deterministic reduction of the 8 split-K slices
__global__ void gram_reduce_kernel() {
    int idx = blockIdx.x * 256 + threadIdx.x;
    if (idx < 2 * 32 * 2304) {
        float s = 0.f;
        #pragma unroll
        for (int p = 0; p < 8; p++) s += d_gramp[(long)p * (2 * 32 * 2304) + idx];
        d_gram[idx] = s;
    }
}

// ---------------- per-(b,c) norms + <q,cn> ----------------
__global__ void diag_kernel() {
    int bc = blockIdx.x;   // b*192 + c
    int b = bc / 192;
    const float* q = d_qkvd + ((long)(b * 576 + (bc - b * 192))) * SP;
    const float* k = q + 192L * SP;
    const float* cn = d_cnf + ((long)bc) * SP;
    float s0 = 0, s1 = 0, s2 = 0, s3 = 0;
    for (int i = threadIdx.x; i < SP; i += 256) {
        float qv = q[i], kv = k[i], cv = cn[i];
        s0 += qv * qv; s1 += kv * kv; s2 += cv * cv; s3 += qv * cv;
    }
    __shared__ float red[4][256];
    int tid = threadIdx.x;
    red[0][tid] = s0; red[1][tid] = s1; red[2][tid] = s2; red[3][tid] = s3;
    __syncthreads();
    for (int off = 128; off > 0; off >>= 1) {
        if (tid < off) {
            #pragma unroll
            for (int j = 0; j < 4; j++) red[j][tid] += red[j][tid + off];
        }
        __syncthreads();
    }
    if (tid < 4) d_normv[bc * 4 + tid] = red[tid][0];
}

// ---------------- logits + softmax -> attn ----------------
__global__ void attn_kernel(const float* __restrict__ temp) {
    int bh = blockIdx.x;
    int b = bh >> 2, h = bh & 3;
    __shared__ float L[48][49];
    __shared__ float qn[48], kn[48], cnn[48], un[48];
    int tid = threadIdx.x;
    if (tid < 48) {
        int bc = b * 192 + h * 48 + tid;
        float nq = d_normv[bc * 4 + 0];
        float nk = d_normv[bc * 4 + 1];
        float nc = d_normv[bc * 4 + 2];
        float dqc = d_normv[bc * 4 + 3];
        float q_n = fmaxf(sqrtf(nq), 1e-12f);
        float k_n = fmaxf(sqrtf(nk), 1e-12f);
        float c_n = fmaxf(sqrtf(nc), 1e-12f);
        float uu = 2.f + 2.f * dqc / (q_n * c_n);   // ||q_hat + cn_hat||^2
        float u_n = fmaxf(sqrtf(fmaxf(uu, 0.f)), 1e-12f);
        qn[tid] = q_n; kn[tid] = k_n; cnn[tid] = c_n; un[tid] = u_n;
    }
    __syncthreads();
    const float* Gqk = d_gram + (long)bh * 2304;
    const float* Gck = d_gram + (long)(32 + bh) * 2304;
    float tp = temp[h];
    for (int idx = tid; idx < 2304; idx += 256) {
        int c = idx / 48, d = idx - c * 48;
        L[c][d] = (Gqk[idx] / qn[c] + Gck[idx] / cnn[c]) / (un[c] * kn[d]) * tp;
    }
    __syncthreads();
    if (tid < 48) {
        float mx = -1e30f;
        #pragma unroll
        for (int d = 0; d < 48; d++) mx = fmaxf(mx, L[tid][d]);
        float e[48];
        float sum = 0.f;
        #pragma unroll
        for (int d = 0; d < 48; d++) { e[d] = expf(L[tid][d] - mx); sum += e[d]; }
        float inv = 1.f / sum;
        #pragma unroll
        for (int d = 0; d < 48; d++)
            d_attn[(long)bh * 2304 + tid * 48 + d] = e[d] * inv;
    }
}

// ---------------- M_b = P * blockdiag(attn_b) in fragment order, tf32-rounded --------------
__global__ void mker_frag(const float* __restrict__ P) {
    int cell = blockIdx.x;                // b*288 + mb*24 + kb8
    int lane = threadIdx.x;
    int b = cell / 288; int r = cell - b * 288;
    int mb = r / 24, kb8 = r - mb * 24;
    int g = lane >> 2, tg = lane & 3;
    int o0 = mb * 16 + g;
    int j0 = kb8 * 8 + tg;
    int j1 = j0 + 4;
    float v[4];
    #pragma unroll
    for (int q = 0; q < 4; q++) {
        int o = o0 + ((q & 1) << 3);
        int j = (q < 2) ? j0 : j1;
        int h = j / 48, d = j - h * 48;
        const float* att = d_attn + ((long)(b * 4 + h)) * 2304 + d;
        const float* pw = P + o * 192 + h * 48;
        float acc = 0.f;
        #pragma unroll
        for (int c2 = 0; c2 < 48; c2++) acc += pw[c2] * att[c2 * 48];
        v[q] = f2tff(acc);
    }
    d_MmatF[(long)cell * 32 + lane] = make_float4(v[0], v[1], v[2], v[3]);
}

// ---------------- launch ----------------
extern "C" void kernel_launch(void* const* d_in, const int* in_sizes, int n_in,
                              void* d_out, int out_size) {
    const float* x     = (const float*)d_in[0];
    const float* cn    = (const float*)d_in[1];
    const float* w1    = (const float*)d_in[2];
    const float* w3    = (const float*)d_in[3];
    const float* qkvw  = (const float*)d_in[4];
    const float* dww   = (const float*)d_in[5];
    const float* projw = (const float*)d_in[6];
    const float* temp  = (const float*)d_in[7];
    float* out = (float*)d_out;

    float *pCnf, *pQkv1, *pQkvd;
    float4 *pWqkvF, *pMF;
    cudaGetSymbolAddress((void**)&pCnf, d_cnf);
    cudaGetSymbolAddress((void**)&pQkv1, d_qkv1);
    cudaGetSymbolAddress((void**)&pQkvd, d_qkvd);
    cudaGetSymbolAddress((void**)&pWqkvF, d_WqkvF);
    cudaGetSymbolAddress((void**)&pMF, d_MmatF);

    compose_w_frag<<<2592, 32>>>(w1, w3);
    swz_qkvw<<<864, 32>>>(qkvw);
    pad_kernel<<<dim3(130, 192, 8), 132>>>(cn);
    // cn_f = composite 3x3 conv, K-groups (dy, ci16) x 3 dx passes
    gemm_conv2<<<dim3(128, 2, 8), 128>>>(pCnf);
    // qkv1 = 1x1 conv, M=576 K=192 (KB8=24)
    gemm_v4<<<dim3(128, 6, 8), 128>>>(pWqkvF, x, pQkv1, 24, 0, 192L * SP, 576L * SP);
    dw_v2<<<dim3(576, 8), 128>>>(dww);
    gram_kernel<<<dim3(8, 2, 32), 128>>>();
    gram_reduce_kernel<<<576, 256>>>();
    diag_kernel<<<1536, 256>>>();
    attn_kernel<<<32, 256>>>(temp);
    mker_frag<<<2304, 32>>>(projw);
    // out = M_b @ v  (v = qkvd channels 384..575), M=192 K=192
    gemm_v4<<<dim3(128, 2, 8), 128>>>(pMF, pQkvd + 384L * SP, out,
                                      24, 12 * 24 * 32, 576L * SP, 192L * SP);
}

// round 9
// speedup vs baseline: 1.7728x; 1.0753x over previous
#include <cuda_runtime.h>
#include <math.h>

#define SP 16384

// ---------------- scratch (device globals; every element rewritten per call) ----------------
__device__ float4 d_WcF[2592 * 32];                // composite conv weight, fragment order, tf32-rounded
__device__ float4 d_WqkvF[36 * 24 * 32];           // qkv weight, fragment order, tf32-rounded
__device__ float4 d_MmatF[8 * 12 * 24 * 32];       // per-batch P*blockdiag(attn), fragment order
__device__ float d_pad[8L * 192 * 130 * 132];      // zero-padded cn, tf32-rounded, row stride 132 (j=w+1)
__device__ float d_cnf[8L * 192 * SP];             // cn feature
__device__ float d_qkv1[8L * 576 * SP];            // qkv after 1x1
__device__ float d_qkvd[8L * 576 * SP];            // qkv after dw 3x3
__device__ float d_gramp[8L * 2 * 32 * 2304];      // split-K gram partials
__device__ float d_gram[2L * 32 * 2304];           // reduced grams (t=0:qk, t=1:ck)
__device__ float d_normv[8 * 192 * 4];             // per (b,c): |q|^2, |k|^2, |cn|^2, <q,cn>
__device__ float d_attn[32 * 2304];                // softmax attn per (b,h)

__device__ __forceinline__ unsigned f2tf(float f) {
    unsigned u;
    asm("cvt.rna.tf32.f32 %0, %1;" : "=r"(u) : "f"(f));
    return u;
}
__device__ __forceinline__ float f2tff(float f) { return __uint_as_float(f2tf(f)); }

__device__ __forceinline__ void mma8(float* acc, const unsigned* a, unsigned b0, unsigned b1) {
    asm volatile(
        "mma.sync.aligned.m16n8k8.row.col.f32.tf32.tf32.f32 "
        "{%0,%1,%2,%3}, {%4,%5,%6,%7}, {%8,%9}, {%0,%1,%2,%3};\n"
        : "+f"(acc[0]), "+f"(acc[1]), "+f"(acc[2]), "+f"(acc[3])
        : "r"(a[0]), "r"(a[1]), "r"(a[2]), "r"(a[3]), "r"(b0), "r"(b1));
}

__device__ __forceinline__ void cpa16(float* smem, const float* g) {
    unsigned d = (unsigned)__cvta_generic_to_shared(smem);
    asm volatile("cp.async.cg.shared.global [%0], [%1], 16;\n" :: "r"(d), "l"(g));
}

// ---------------- composite conv weight, fragment order ----------------
// cell = (((mb*3+dy)*12+cib)*3+dx)*2+ks8 ; lane gives (g,tg).
// value(o,ci) = sum_m W3[o,m,tap]*W1[m,ci], tap = dy*3+dx.
__global__ void compose_w_frag(const float* __restrict__ w1, const float* __restrict__ w3) {
    int cell = blockIdx.x;
    int lane = threadIdx.x;
    int ks8 = cell & 1;
    int c2 = cell >> 1;
    int dx = c2 % 3;  int c3 = c2 / 3;
    int cib = c3 % 12; int c4 = c3 / 12;
    int dy = c4 % 3;  int mb = c4 / 3;
    int g = lane >> 2, tg = lane & 3;
    int tap = dy * 3 + dx;
    int o0 = mb * 16 + g;
    int ci0 = cib * 16 + ks8 * 8 + tg;
    float s0 = 0, s1 = 0, s2 = 0, s3 = 0;
    for (int m = 0; m < 192; m++) {
        float a0 = w3[(o0 * 192 + m) * 9 + tap];
        float a1 = w3[((o0 + 8) * 192 + m) * 9 + tap];
        float b0 = w1[m * 192 + ci0];
        float b1 = w1[m * 192 + ci0 + 4];
        s0 += a0 * b0; s1 += a1 * b0; s2 += a0 * b1; s3 += a1 * b1;
    }
    d_WcF[cell * 32 + lane] = make_float4(f2tff(s0), f2tff(s1), f2tff(s2), f2tff(s3));
}

// ---------------- qkv weight fragment swizzle ----------------
__global__ void swz_qkvw(const float* __restrict__ w) {
    int mb = blockIdx.x / 24, kb8 = blockIdx.x % 24;
    int lane = threadIdx.x;
    int g = lane >> 2, tg = lane & 3;
    int o0 = mb * 16 + g, k0 = kb8 * 8 + tg;
    float4 v;
    v.x = f2tff(w[o0 * 192 + k0]);
    v.y = f2tff(w[(o0 + 8) * 192 + k0]);
    v.z = f2tff(w[o0 * 192 + k0 + 4]);
    v.w = f2tff(w[(o0 + 8) * 192 + k0 + 4]);
    d_WqkvF[(mb * 24 + kb8) * 32 + lane] = v;
}

// ---------------- zero-padded tf32-rounded copy of cn: [b][c][130][132], j = w+1 -----------
__global__ void pad_kernel(const float* __restrict__ cn) {
    int j = threadIdx.x;      // 0..131
    int hh = blockIdx.x;      // 0..129
    int c = blockIdx.y;
    int b = blockIdx.z;
    float v = 0.f;
    if (hh >= 1 && hh <= 128 && j >= 1 && j <= 128)
        v = f2tff(cn[((long)(b * 192 + c)) * SP + (hh - 1) * 128 + (j - 1)]);
    d_pad[(((long)(b * 192 + c)) * 130 + hh) * 132 + j] = v;
}

// ---------------- conv GEMM v2: 36 K-groups of (dy, ci-block); one B tile serves 3 dx ------
// Block 96(M) x 128(N=one image row), 128 thr, 4 warps, warp tile 48x64.
// A fragments direct from d_WcF (LDG.128, pre-tf32). B pre-rounded in d_pad -> no CVT.
// Single barrier per K-group (double buffer: top-of-loop wait+sync covers both hazards).
__global__ void __launch_bounds__(128, 3) gemm_conv2(float* __restrict__ C)
{
    __shared__ float Bs[2][16 * 136];

    const int bz = blockIdx.z;
    const int h_row = blockIdx.x;        // spatial row 0..127
    const int n0 = h_row << 7;
    const int m0 = blockIdx.y * 96;
    const int mb0 = blockIdx.y * 6;
    const int tid = threadIdx.x;
    float* Cb = C + (long)bz * 192 * SP;

    const int warp = tid >> 5, lane = tid & 31;
    const int wm = (warp >> 1) * 48;
    const int wn = (warp & 1) << 6;
    const int g = lane >> 2, tg = lane & 3;
    const int mwb = (warp >> 1) * 3;     // first 16-row block of this warp

    float acc[3][8][4];
    #pragma unroll
    for (int i = 0; i < 3; i++)
        #pragma unroll
        for (int j = 0; j < 8; j++)
            #pragma unroll
            for (int l = 0; l < 4; l++) acc[i][j][l] = 0.f;

    auto issueB = [&](int gg, int buf) {
        int dy = gg / 12;
        int ci0 = (gg - dy * 12) << 4;
        const float* base = d_pad + (((long)(bz * 192 + ci0)) * 130 + h_row + dy) * 132;
        #pragma unroll
        for (int it = 0; it < 5; it++) {
            int idx = tid + (it << 7);
            if (idx < 528) {
                int kr = idx / 33;
                int q = (idx - kr * 33) << 2;
                cpa16(&Bs[buf][kr * 136 + q], base + (long)kr * (130 * 132) + q);
            }
        }
        asm volatile("cp.async.commit_group;\n");
    };

    auto pass = [&](int buf, int dy, int cib, int dx) {
        #pragma unroll
        for (int ks8 = 0; ks8 < 2; ks8++) {
            unsigned af[3][4];
            #pragma unroll
            for (int mt = 0; mt < 3; mt++) {
                int cell = ((((mb0 + mwb + mt) * 3 + dy) * 12 + cib) * 3 + dx) * 2 + ks8;
                float4 a = d_WcF[cell * 32 + lane];
                af[mt][0] = __float_as_uint(a.x);
                af[mt][1] = __float_as_uint(a.y);
                af[mt][2] = __float_as_uint(a.z);
                af[mt][3] = __float_as_uint(a.w);
            }
            int kr = ks8 << 3;
            #pragma unroll
            for (int nt = 0; nt < 8; nt++) {
                int n = wn + (nt << 3) + g + dx;
                unsigned b0 = __float_as_uint(Bs[buf][(kr + tg) * 136 + n]);
                unsigned b1 = __float_as_uint(Bs[buf][(kr + tg + 4) * 136 + n]);
                #pragma unroll
                for (int mt = 0; mt < 3; mt++)
                    mma8(acc[mt][nt], af[mt], b0, b1);
            }
        }
    };

    issueB(0, 0);
    for (int gg = 0; gg < 36; gg++) {
        asm volatile("cp.async.wait_group 0;\n");
        __syncthreads();
        if (gg + 1 < 36) issueB(gg + 1, (gg + 1) & 1);
        int dy = gg / 12;
        int cib = gg - dy * 12;
        pass(gg & 1, dy, cib, 0);
        pass(gg & 1, dy, cib, 1);
        pass(gg & 1, dy, cib, 2);
    }

    #pragma unroll
    for (int mt = 0; mt < 3; mt++)
        #pragma unroll
        for (int nt = 0; nt < 8; nt++) {
            long row = m0 + wm + (mt << 4) + g;
            int col = n0 + wn + (nt << 3) + (tg << 1);
            *reinterpret_cast<float2*>(Cb + row * SP + col) =
                make_float2(acc[mt][nt][0], acc[mt][nt][1]);
            *reinterpret_cast<float2*>(Cb + (row + 8) * SP + col) =
                make_float2(acc[mt][nt][2], acc[mt][nt][3]);
        }
}

// ---------------- dense tf32 GEMM v4: A-frag direct LDG, B via cp.async smem ----------------
// Block 96(M) x 128(N) x 16(K), 128 thr, 4 warps, warp tile 48x64; single barrier per tile.
__global__ void __launch_bounds__(128, 3) gemm_v4(
    const float4* __restrict__ Af, const float* __restrict__ B, float* __restrict__ C,
    int KB8, long sAf, long sB, long sC)
{
    __shared__ float Bs[2][16 * 136];

    const int bz = blockIdx.z;
    const int n0 = blockIdx.x << 7;
    const int m0 = blockIdx.y * 96;
    const int mb0 = blockIdx.y * 6;
    const int tid = threadIdx.x;
    const float4* Ab = Af + (long)bz * sAf;
    const float* Bb = B + (long)bz * sB;
    float* Cb = C + (long)bz * sC;

    const int bk = tid >> 4;            // 0..7
    const int bn = (tid & 15) << 3;     // 0..120
    const int warp = tid >> 5, lane = tid & 31;
    const int wm = (warp >> 1) * 48;
    const int wn = (warp & 1) << 6;
    const int g = lane >> 2, tg = lane & 3;
    const int mwb = (warp >> 1) * 3;

    float acc[3][8][4];
    #pragma unroll
    for (int i = 0; i < 3; i++)
        #pragma unroll
        for (int j = 0; j < 8; j++)
            #pragma unroll
            for (int l = 0; l < 4; l++) acc[i][j][l] = 0.f;

    auto issue = [&](int t, int buf) {
        int k0 = t << 4;
        #pragma unroll
        for (int i = 0; i < 2; i++) {
            int kr = bk + (i << 3);
            const float* p = Bb + (long)(k0 + kr) * SP + n0 + bn;
            cpa16(&Bs[buf][kr * 136 + bn], p);
            cpa16(&Bs[buf][kr * 136 + bn + 4], p + 4);
        }
        asm volatile("cp.async.commit_group;\n");
    };

    auto compute = [&](int buf, int t) {
        #pragma unroll
        for (int ks8 = 0; ks8 < 2; ks8++) {
            int kb8 = (t << 1) + ks8;
            unsigned af[3][4];
            #pragma unroll
            for (int mt = 0; mt < 3; mt++) {
                float4 a = Ab[((mb0 + mwb + mt) * KB8 + kb8) * 32 + lane];
                af[mt][0] = __float_as_uint(a.x);
                af[mt][1] = __float_as_uint(a.y);
                af[mt][2] = __float_as_uint(a.z);
                af[mt][3] = __float_as_uint(a.w);
            }
            int kr = ks8 << 3;
            #pragma unroll
            for (int nt = 0; nt < 8; nt++) {
                int n = wn + (nt << 3) + g;
                unsigned b0 = f2tf(Bs[buf][(kr + tg) * 136 + n]);
                unsigned b1 = f2tf(Bs[buf][(kr + tg + 4) * 136 + n]);
                #pragma unroll
                for (int mt = 0; mt < 3; mt++)
                    mma8(acc[mt][nt], af[mt], b0, b1);
            }
        }
    };

    const int T = KB8 >> 1;
    issue(0, 0);
    for (int t = 0; t < T; t++) {
        asm volatile("cp.async.wait_group 0;\n");
        __syncthreads();
        if (t + 1 < T) issue(t + 1, (t + 1) & 1);
        compute(t & 1, t);
    }

    #pragma unroll
    for (int mt = 0; mt < 3; mt++)
        #pragma unroll
        for (int nt = 0; nt < 8; nt++) {
            long row = m0 + wm + (mt << 4) + g;
            int col = n0 + wn + (nt << 3) + (tg << 1);
            *reinterpret_cast<float2*>(Cb + row * SP + col) =
                make_float2(acc[mt][nt][0], acc[mt][nt][1]);
            *reinterpret_cast<float2*>(Cb + (row + 8) * SP + col) =
                make_float2(acc[mt][nt][2], acc[mt][nt][3]);
        }
}

// ---------------- depthwise 3x3: barrier-free, register row window, direct L1 loads --------
__global__ void __launch_bounds__(128) dw_v3(const float* __restrict__ dww) {
    int w = threadIdx.x;      // column 0..127
    int o = blockIdx.x;
    int b = blockIdx.y;
    const float* src = d_qkv1 + ((long)(b * 576 + o)) * SP;
    float* dst = d_qkvd + ((long)(b * 576 + o)) * SP;
    float wg[9];
    #pragma unroll
    for (int t = 0; t < 9; t++) wg[t] = __ldg(dww + o * 9 + t);
    const bool hl = (w > 0), hr = (w < 127);

    float al = 0.f, am = 0.f, ar = 0.f;            // row h-1
    float bl, bm, br;                               // row h
    bl = hl ? src[w - 1] : 0.f;
    bm = src[w];
    br = hr ? src[w + 1] : 0.f;

    #pragma unroll 4
    for (int h = 0; h < 128; h++) {
        float cl = 0.f, cm = 0.f, cr = 0.f;        // row h+1
        if (h < 127) {
            const float* r = src + (h + 1) * 128;
            cl = hl ? r[w - 1] : 0.f;
            cm = r[w];
            cr = hr ? r[w + 1] : 0.f;
        }
        float acc = wg[0] * al + wg[1] * am + wg[2] * ar
                  + wg[3] * bl + wg[4] * bm + wg[5] * br
                  + wg[6] * cl + wg[7] * cm + wg[8] * cr;
        dst[h * 128 + w] = acc;
        al = bl; am = bm; ar = br;
        bl = cl; bm = cm; br = cr;
    }
}

// ---------------- split-K Gram partials: per (slice,t,bh) a 48x48 block ----------------
__global__ void __launch_bounds__(128) gram_kernel() {
    __shared__ unsigned Sa[32 * 56];
    __shared__ unsigned Sb[32 * 56];
    int slice = blockIdx.x;   // 0..7
    int t = blockIdx.y;       // 0..1
    int bh = blockIdx.z;      // 0..31
    int b = bh >> 2, h = bh & 3;
    const float* Arow = t ? (d_cnf + ((long)(b * 192 + h * 48)) * SP)
                          : (d_qkvd + ((long)(b * 576 + h * 48)) * SP);
    const float* Brow = d_qkvd + ((long)(b * 576 + 192 + h * 48)) * SP;
    int tid = threadIdx.x;
    int warp = tid >> 5, lane = tid & 31, g = lane >> 2, tg = lane & 3;
    float acc[6][4];
    #pragma unroll
    for (int i = 0; i < 6; i++)
        #pragma unroll
        for (int j = 0; j < 4; j++) acc[i][j] = 0.f;

    int kbase = slice * 2048;
    for (int kb = 0; kb < 2048; kb += 32) {
        __syncthreads();
        #pragma unroll
        for (int it = 0; it < 12; it++) {
            int idx = tid + it * 128;
            int m = idx >> 5, kk = idx & 31;
            Sa[kk * 56 + m] = f2tf(Arow[(long)m * SP + kbase + kb + kk]);
            Sb[kk * 56 + m] = f2tf(Brow[(long)m * SP + kbase + kb + kk]);
        }
        __syncthreads();
        if (warp < 3) {
            #pragma unroll
            for (int ks = 0; ks < 32; ks += 8) {
                unsigned a[4];
                int m = warp << 4;
                a[0] = Sa[(ks + tg) * 56 + m + g];
                a[1] = Sa[(ks + tg) * 56 + m + g + 8];
                a[2] = Sa[(ks + tg + 4) * 56 + m + g];
                a[3] = Sa[(ks + tg + 4) * 56 + m + g + 8];
                #pragma unroll
                for (int nt = 0; nt < 6; nt++) {
                    unsigned b0 = Sb[(ks + tg) * 56 + (nt << 3) + g];
                    unsigned b1 = Sb[(ks + tg + 4) * 56 + (nt << 3) + g];
                    mma8(acc[nt], a, b0, b1);
                }
            }
        }
    }
    if (warp < 3) {
        float* out = d_gramp + (((long)slice * 2 + t) * 32 + bh) * 2304;
        #pragma unroll
        for (int nt = 0; nt < 6; nt++) {
            int r = (warp << 4) + g;
            int col = (nt << 3) + (tg << 1);
            out[r * 48 + col] = acc[nt][0];
            out[r * 48 + col + 1] = acc[nt][1];
            out[(r + 8) * 48 + col] = acc[nt][2];
            out[(r + 8) * 48 + col + 1] = acc[nt][3];
        }
    }
}

// deterministic reduction of the 8 split-K slices
__global__ void gram_reduce_kernel() {
    int idx = blockIdx.x * 256 + threadIdx.x;
    if (idx < 2 * 32 * 2304) {
        float s = 0.f;
        #pragma unroll
        for (int p = 0; p < 8; p++) s += d_gramp[(long)p * (2 * 32 * 2304) + idx];
        d_gram[idx] = s;
    }
}

// ---------------- per-(b,c) norms + <q,cn>, float4 loads ----------------
__global__ void diag_kernel() {
    int bc = blockIdx.x;   // b*192 + c
    int b = bc / 192;
    const float4* q = (const float4*)(d_qkvd + ((long)(b * 576 + (bc - b * 192))) * SP);
    const float4* k = (const float4*)((const float*)q + 192L * SP);
    const float4* cn = (const float4*)(d_cnf + ((long)bc) * SP);
    float s0 = 0, s1 = 0, s2 = 0, s3 = 0;
    for (int i = threadIdx.x; i < SP / 4; i += 256) {
        float4 qv = q[i], kv = k[i], cv = cn[i];
        s0 += qv.x * qv.x + qv.y * qv.y + qv.z * qv.z + qv.w * qv.w;
        s1 += kv.x * kv.x + kv.y * kv.y + kv.z * kv.z + kv.w * kv.w;
        s2 += cv.x * cv.x + cv.y * cv.y + cv.z * cv.z + cv.w * cv.w;
        s3 += qv.x * cv.x + qv.y * cv.y + qv.z * cv.z + qv.w * cv.w;
    }
    __shared__ float red[4][256];
    int tid = threadIdx.x;
    red[0][tid] = s0; red[1][tid] = s1; red[2][tid] = s2; red[3][tid] = s3;
    __syncthreads();
    for (int off = 128; off > 0; off >>= 1) {
        if (tid < off) {
            #pragma unroll
            for (int j = 0; j < 4; j++) red[j][tid] += red[j][tid + off];
        }
        __syncthreads();
    }
    if (tid < 4) d_normv[bc * 4 + tid] = red[tid][0];
}

// ---------------- logits + softmax -> attn ----------------
__global__ void attn_kernel(const float* __restrict__ temp) {
    int bh = blockIdx.x;
    int b = bh >> 2, h = bh & 3;
    __shared__ float L[48][49];
    __shared__ float qn[48], kn[48], cnn[48], un[48];
    int tid = threadIdx.x;
    if (tid < 48) {
        int bc = b * 192 + h * 48 + tid;
        float nq = d_normv[bc * 4 + 0];
        float nk = d_normv[bc * 4 + 1];
        float nc = d_normv[bc * 4 + 2];
        float dqc = d_normv[bc * 4 + 3];
        float q_n = fmaxf(sqrtf(nq), 1e-12f);
        float k_n = fmaxf(sqrtf(nk), 1e-12f);
        float c_n = fmaxf(sqrtf(nc), 1e-12f);
        float uu = 2.f + 2.f * dqc / (q_n * c_n);   // ||q_hat + cn_hat||^2
        float u_n = fmaxf(sqrtf(fmaxf(uu, 0.f)), 1e-12f);
        qn[tid] = q_n; kn[tid] = k_n; cnn[tid] = c_n; un[tid] = u_n;
    }
    __syncthreads();
    const float* Gqk = d_gram + (long)bh * 2304;
    const float* Gck = d_gram + (long)(32 + bh) * 2304;
    float tp = temp[h];
    for (int idx = tid; idx < 2304; idx += 256) {
        int c = idx / 48, d = idx - c * 48;
        L[c][d] = (Gqk[idx] / qn[c] + Gck[idx] / cnn[c]) / (un[c] * kn[d]) * tp;
    }
    __syncthreads();
    if (tid < 48) {
        float mx = -1e30f;
        #pragma unroll
        for (int d = 0; d < 48; d++) mx = fmaxf(mx, L[tid][d]);
        float e[48];
        float sum = 0.f;
        #pragma unroll
        for (int d = 0; d < 48; d++) { e[d] = expf(L[tid][d] - mx); sum += e[d]; }
        float inv = 1.f / sum;
        #pragma unroll
        for (int d = 0; d < 48; d++)
            d_attn[(long)bh * 2304 + tid * 48 + d] = e[d] * inv;
    }
}

// ---------------- M_b = P * blockdiag(attn_b) in fragment order, tf32-rounded --------------
__global__ void mker_frag(const float* __restrict__ P) {
    int cell = blockIdx.x;                // b*288 + mb*24 + kb8
    int lane = threadIdx.x;
    int b = cell / 288; int r = cell - b * 288;
    int mb = r / 24, kb8 = r - mb * 24;
    int g = lane >> 2, tg = lane & 3;
    int o0 = mb * 16 + g;
    int j0 = kb8 * 8 + tg;
    int j1 = j0 + 4;
    float v[4];
    #pragma unroll
    for (int q = 0; q < 4; q++) {
        int o = o0 + ((q & 1) << 3);
        int j = (q < 2) ? j0 : j1;
        int h = j / 48, d = j - h * 48;
        const float* att = d_attn + ((long)(b * 4 + h)) * 2304 + d;
        const float* pw = P + o * 192 + h * 48;
        float acc = 0.f;
        #pragma unroll
        for (int c2 = 0; c2 < 48; c2++) acc += pw[c2] * att[c2 * 48];
        v[q] = f2tff(acc);
    }
    d_MmatF[(long)cell * 32 + lane] = make_float4(v[0], v[1], v[2], v[3]);
}

// ---------------- launch ----------------
extern "C" void kernel_launch(void* const* d_in, const int* in_sizes, int n_in,
                              void* d_out, int out_size) {
    const float* x     = (const float*)d_in[0];
    const float* cn    = (const float*)d_in[1];
    const float* w1    = (const float*)d_in[2];
    const float* w3    = (const float*)d_in[3];
    const float* qkvw  = (const float*)d_in[4];
    const float* dww   = (const float*)d_in[5];
    const float* projw = (const float*)d_in[6];
    const float* temp  = (const float*)d_in[7];
    float* out = (float*)d_out;

    float *pCnf, *pQkv1, *pQkvd;
    float4 *pWqkvF, *pMF;
    cudaGetSymbolAddress((void**)&pCnf, d_cnf);
    cudaGetSymbolAddress((void**)&pQkv1, d_qkv1);
    cudaGetSymbolAddress((void**)&pQkvd, d_qkvd);
    cudaGetSymbolAddress((void**)&pWqkvF, d_WqkvF);
    cudaGetSymbolAddress((void**)&pMF, d_MmatF);

    compose_w_frag<<<2592, 32>>>(w1, w3);
    swz_qkvw<<<864, 32>>>(qkvw);
    pad_kernel<<<dim3(130, 192, 8), 132>>>(cn);
    // cn_f = composite 3x3 conv, K-groups (dy, ci16) x 3 dx passes
    gemm_conv2<<<dim3(128, 2, 8), 128>>>(pCnf);
    // qkv1 = 1x1 conv, M=576 K=192 (KB8=24)
    gemm_v4<<<dim3(128, 6, 8), 128>>>(pWqkvF, x, pQkv1, 24, 0, 192L * SP, 576L * SP);
    dw_v3<<<dim3(576, 8), 128>>>(dww);
    gram_kernel<<<dim3(8, 2, 32), 128>>>();
    gram_reduce_kernel<<<576, 256>>>();
    diag_kernel<<<1536, 256>>>();
    attn_kernel<<<32, 256>>>(temp);
    mker_frag<<<2304, 32>>>(projw);
    // out = M_b @ v  (v = qkvd channels 384..575), M=192 K=192
    gemm_v4<<<dim3(128, 2, 8), 128>>>(pMF, pQkvd + 384L * SP, out,
                                      24, 12 * 24 * 32, 576L * SP, 192L * SP);
}

// round 16
// speedup vs baseline: 1.8412x; 1.0386x over previous
#include <cuda_runtime.h>
#include <cstdint>
#include <stdint.h>
#include <math.h>

#define SP 16384

// ---------------- scratch (device globals; every element rewritten per call) ----------------
__device__ float4 d_WcF[2592 * 32];                // composite conv weight, fragment order, tf32-rounded
__device__ float4 d_WqkvF[36 * 24 * 32];           // qkv weight, fragment order, tf32-rounded
__device__ float4 d_MmatF[8 * 12 * 24 * 32];       // per-batch P*blockdiag(attn), fragment order
__device__ float d_pad[8L * 192 * 130 * 132];      // zero-padded cn, tf32-rounded, row stride 132 (j=w+1)
__device__ float d_cnf[8L * 192 * SP];             // cn feature
__device__ float d_qkv1[8L * 576 * SP];            // qkv after 1x1
__device__ float d_qkvd[8L * 576 * SP];            // qkv after dw 3x3
__device__ float d_gramp[8L * 2 * 32 * 2304];      // split-K gram partials
__device__ float d_gram[2L * 32 * 2304];           // reduced grams (t=0:qk, t=1:ck)
__device__ float d_normv[8 * 192 * 4];             // per (b,c): |q|^2, |k|^2, |cn|^2, <q,cn>
__device__ float d_attn[32 * 2304];                // softmax attn per (b,h)

__device__ __forceinline__ unsigned f2tf(float f) {
    unsigned u;
    asm("cvt.rna.tf32.f32 %0, %1;" : "=r"(u) : "f"(f));
    return u;
}
__device__ __forceinline__ float f2tff(float f) { return __uint_as_float(f2tf(f)); }

__device__ __forceinline__ void mma8(float* acc, const unsigned* a, unsigned b0, unsigned b1) {
    asm volatile(
        "mma.sync.aligned.m16n8k8.row.col.f32.tf32.tf32.f32 "
        "{%0,%1,%2,%3}, {%4,%5,%6,%7}, {%8,%9}, {%0,%1,%2,%3};\n"
        : "+f"(acc[0]), "+f"(acc[1]), "+f"(acc[2]), "+f"(acc[3])
        : "r"(a[0]), "r"(a[1]), "r"(a[2]), "r"(a[3]), "r"(b0), "r"(b1));
}

__device__ __forceinline__ void cpa16(float* smem, const float* g) {
    unsigned d = (unsigned)__cvta_generic_to_shared(smem);
    asm volatile("cp.async.cg.shared.global [%0], [%1], 16;\n" :: "r"(d), "l"(g));
}

// ---------------- composite conv weight, fragment order ----------------
// cell = (((mb*3+dy)*12+cib)*3+dx)*2+ks8 ; lane gives (g,tg).
__global__ void compose_w_frag(const float* __restrict__ w1, const float* __restrict__ w3) {
    int cell = blockIdx.x;
    int lane = threadIdx.x;
    int ks8 = cell & 1;
    int c2 = cell >> 1;
    int dx = c2 % 3;  int c3 = c2 / 3;
    int cib = c3 % 12; int c4 = c3 / 12;
    int dy = c4 % 3;  int mb = c4 / 3;
    int g = lane >> 2, tg = lane & 3;
    int tap = dy * 3 + dx;
    int o0 = mb * 16 + g;
    int ci0 = cib * 16 + ks8 * 8 + tg;
    float s0 = 0, s1 = 0, s2 = 0, s3 = 0;
    for (int m = 0; m < 192; m++) {
        float a0 = w3[(o0 * 192 + m) * 9 + tap];
        float a1 = w3[((o0 + 8) * 192 + m) * 9 + tap];
        float b0 = w1[m * 192 + ci0];
        float b1 = w1[m * 192 + ci0 + 4];
        s0 += a0 * b0; s1 += a1 * b0; s2 += a0 * b1; s3 += a1 * b1;
    }
    d_WcF[cell * 32 + lane] = make_float4(f2tff(s0), f2tff(s1), f2tff(s2), f2tff(s3));
}

// ---------------- qkv weight fragment swizzle ----------------
__global__ void swz_qkvw(const float* __restrict__ w) {
    int mb = blockIdx.x / 24, kb8 = blockIdx.x % 24;
    int lane = threadIdx.x;
    int g = lane >> 2, tg = lane & 3;
    int o0 = mb * 16 + g, k0 = kb8 * 8 + tg;
    float4 v;
    v.x = f2tff(w[o0 * 192 + k0]);
    v.y = f2tff(w[(o0 + 8) * 192 + k0]);
    v.z = f2tff(w[o0 * 192 + k0 + 4]);
    v.w = f2tff(w[(o0 + 8) * 192 + k0 + 4]);
    d_WqkvF[(mb * 24 + kb8) * 32 + lane] = v;
}

// ---------------- zero-padded tf32-rounded copy of cn: [b][c][130][132], j = w+1 -----------
__global__ void pad_kernel(const float* __restrict__ cn) {
    int j = threadIdx.x;      // 0..131
    int hh = blockIdx.x;      // 0..129
    int c = blockIdx.y;
    int b = blockIdx.z;
    float v = 0.f;
    if (hh >= 1 && hh <= 128 && j >= 1 && j <= 128)
        v = f2tff(cn[((long)(b * 192 + c)) * SP + (hh - 1) * 128 + (j - 1)]);
    d_pad[(((long)(b * 192 + c)) * 130 + hh) * 132 + j] = v;
}

// ---------------- FAT kernel: conv (y<2) + qkv 1x1 GEMM (y>=2) in one grid ----------------
// Both branches: 128 thr, 4 warps, warp tile 48x64, same smem shape, 3 CTAs/SM.
// Interleaving lets the SM co-schedule tensor-saturating conv CTAs with qkv CTAs.
__global__ void __launch_bounds__(128, 3) fat_conv_qkv(
    const float4* __restrict__ WqkvF, const float* __restrict__ x,
    float* __restrict__ Ccnf, float* __restrict__ Cqkv)
{
    __shared__ float Bs[2][16 * 136];

    const int bz = blockIdx.z;
    const int tid = threadIdx.x;
    const int warp = tid >> 5, lane = tid & 31;
    const int g = lane >> 2, tg = lane & 3;
    const int wm = (warp >> 1) * 48;
    const int wn = (warp & 1) << 6;
    const int mwb = (warp >> 1) * 3;

    float acc[3][8][4];
    #pragma unroll
    for (int i = 0; i < 3; i++)
        #pragma unroll
        for (int j = 0; j < 8; j++)
            #pragma unroll
            for (int l = 0; l < 4; l++) acc[i][j][l] = 0.f;

    if (blockIdx.y < 2) {
        // ===== conv branch: one image row, 36 K-groups (dy, ci16) x 3 dx passes =====
        const int h_row = blockIdx.x;
        const int n0 = h_row << 7;
        const int m0 = blockIdx.y * 96;
        const int mb0 = blockIdx.y * 6;
        float* Cb = Ccnf + (long)bz * 192 * SP;

        auto issueB = [&](int gg, int buf) {
            int dy = gg / 12;
            int ci0 = (gg - dy * 12) << 4;
            const float* base = d_pad + (((long)(bz * 192 + ci0)) * 130 + h_row + dy) * 132;
            #pragma unroll
            for (int it = 0; it < 5; it++) {
                int idx = tid + (it << 7);
                if (idx < 528) {
                    int kr = idx / 33;
                    int q = (idx - kr * 33) << 2;
                    cpa16(&Bs[buf][kr * 136 + q], base + (long)kr * (130 * 132) + q);
                }
            }
            asm volatile("cp.async.commit_group;\n");
        };

        auto pass = [&](int buf, int dy, int cib, int dx) {
            #pragma unroll
            for (int ks8 = 0; ks8 < 2; ks8++) {
                unsigned af[3][4];
                #pragma unroll
                for (int mt = 0; mt < 3; mt++) {
                    int cell = ((((mb0 + mwb + mt) * 3 + dy) * 12 + cib) * 3 + dx) * 2 + ks8;
                    float4 a = d_WcF[cell * 32 + lane];
                    af[mt][0] = __float_as_uint(a.x);
                    af[mt][1] = __float_as_uint(a.y);
                    af[mt][2] = __float_as_uint(a.z);
                    af[mt][3] = __float_as_uint(a.w);
                }
                int kr = ks8 << 3;
                #pragma unroll
                for (int nt = 0; nt < 8; nt++) {
                    int n = wn + (nt << 3) + g + dx;
                    unsigned b0 = __float_as_uint(Bs[buf][(kr + tg) * 136 + n]);
                    unsigned b1 = __float_as_uint(Bs[buf][(kr + tg + 4) * 136 + n]);
                    #pragma unroll
                    for (int mt = 0; mt < 3; mt++)
                        mma8(acc[mt][nt], af[mt], b0, b1);
                }
            }
        };

        issueB(0, 0);
        for (int gg = 0; gg < 36; gg++) {
            asm volatile("cp.async.wait_group 0;\n");
            __syncthreads();
            if (gg + 1 < 36) issueB(gg + 1, (gg + 1) & 1);
            int dy = gg / 12;
            int cib = gg - dy * 12;
            pass(gg & 1, dy, cib, 0);
            pass(gg & 1, dy, cib, 1);
            pass(gg & 1, dy, cib, 2);
        }

        #pragma unroll
        for (int mt = 0; mt < 3; mt++)
            #pragma unroll
            for (int nt = 0; nt < 8; nt++) {
                long row = m0 + wm + (mt << 4) + g;
                int col = n0 + wn + (nt << 3) + (tg << 1);
                *reinterpret_cast<float2*>(Cb + row * SP + col) =
                    make_float2(acc[mt][nt][0], acc[mt][nt][1]);
                *reinterpret_cast<float2*>(Cb + (row + 8) * SP + col) =
                    make_float2(acc[mt][nt][2], acc[mt][nt][3]);
            }
    } else {
        // ===== qkv 1x1 GEMM branch: M=576 K=192 (KB8=24) =====
        const int n0 = blockIdx.x << 7;
        const int m0 = (blockIdx.y - 2) * 96;
        const int mb0 = (blockIdx.y - 2) * 6;
        const float* Bb = x + (long)bz * 192 * SP;
        float* Cb = Cqkv + (long)bz * 576 * SP;
        const int bk = tid >> 4;
        const int bn = (tid & 15) << 3;

        auto issue = [&](int t, int buf) {
            int k0 = t << 4;
            #pragma unroll
            for (int i = 0; i < 2; i++) {
                int kr = bk + (i << 3);
                const float* p = Bb + (long)(k0 + kr) * SP + n0 + bn;
                cpa16(&Bs[buf][kr * 136 + bn], p);
                cpa16(&Bs[buf][kr * 136 + bn + 4], p + 4);
            }
            asm volatile("cp.async.commit_group;\n");
        };

        auto compute = [&](int buf, int t) {
            #pragma unroll
            for (int ks8 = 0; ks8 < 2; ks8++) {
                int kb8 = (t << 1) + ks8;
                unsigned af[3][4];
                #pragma unroll
                for (int mt = 0; mt < 3; mt++) {
                    float4 a = WqkvF[((mb0 + mwb + mt) * 24 + kb8) * 32 + lane];
                    af[mt][0] = __float_as_uint(a.x);
                    af[mt][1] = __float_as_uint(a.y);
                    af[mt][2] = __float_as_uint(a.z);
                    af[mt][3] = __float_as_uint(a.w);
                }
                int kr = ks8 << 3;
                #pragma unroll
                for (int nt = 0; nt < 8; nt++) {
                    int n = wn + (nt << 3) + g;
                    unsigned b0 = f2tf(Bs[buf][(kr + tg) * 136 + n]);
                    unsigned b1 = f2tf(Bs[buf][(kr + tg + 4) * 136 + n]);
                    #pragma unroll
                    for (int mt = 0; mt < 3; mt++)
                        mma8(acc[mt][nt], af[mt], b0, b1);
                }
            }
        };

        issue(0, 0);
        for (int t = 0; t < 12; t++) {
            asm volatile("cp.async.wait_group 0;\n");
            __syncthreads();
            if (t + 1 < 12) issue(t + 1, (t + 1) & 1);
            compute(t & 1, t);
        }

        #pragma unroll
        for (int mt = 0; mt < 3; mt++)
            #pragma unroll
            for (int nt = 0; nt < 8; nt++) {
                long row = m0 + wm + (mt << 4) + g;
                int col = n0 + wn + (nt << 3) + (tg << 1);
                *reinterpret_cast<float2*>(Cb + row * SP + col) =
                    make_float2(acc[mt][nt][0], acc[mt][nt][1]);
                *reinterpret_cast<float2*>(Cb + (row + 8) * SP + col) =
                    make_float2(acc[mt][nt][2], acc[mt][nt][3]);
            }
    }
}

// ---------------- dense tf32 GEMM v4 (final M_b @ v) ----------------
__global__ void __launch_bounds__(128, 3) gemm_v4(
    const float4* __restrict__ Af, const float* __restrict__ B, float* __restrict__ C,
    int KB8, long sAf, long sB, long sC)
{
    __shared__ float Bs[2][16 * 136];

    const int bz = blockIdx.z;
    const int n0 = blockIdx.x << 7;
    const int m0 = blockIdx.y * 96;
    const int mb0 = blockIdx.y * 6;
    const int tid = threadIdx.x;
    const float4* Ab = Af + (long)bz * sAf;
    const float* Bb = B + (long)bz * sB;
    float* Cb = C + (long)bz * sC;

    const int bk = tid >> 4;
    const int bn = (tid & 15) << 3;
    const int warp = tid >> 5, lane = tid & 31;
    const int wm = (warp >> 1) * 48;
    const int wn = (warp & 1) << 6;
    const int g = lane >> 2, tg = lane & 3;
    const int mwb = (warp >> 1) * 3;

    float acc[3][8][4];
    #pragma unroll
    for (int i = 0; i < 3; i++)
        #pragma unroll
        for (int j = 0; j < 8; j++)
            #pragma unroll
            for (int l = 0; l < 4; l++) acc[i][j][l] = 0.f;

    auto issue = [&](int t, int buf) {
        int k0 = t << 4;
        #pragma unroll
        for (int i = 0; i < 2; i++) {
            int kr = bk + (i << 3);
            const float* p = Bb + (long)(k0 + kr) * SP + n0 + bn;
            cpa16(&Bs[buf][kr * 136 + bn], p);
            cpa16(&Bs[buf][kr * 136 + bn + 4], p + 4);
        }
        asm volatile("cp.async.commit_group;\n");
    };

    auto compute = [&](int buf, int t) {
        #pragma unroll
        for (int ks8 = 0; ks8 < 2; ks8++) {
            int kb8 = (t << 1) + ks8;
            unsigned af[3][4];
            #pragma unroll
            for (int mt = 0; mt < 3; mt++) {
                float4 a = Ab[((mb0 + mwb + mt) * KB8 + kb8) * 32 + lane];
                af[mt][0] = __float_as_uint(a.x);
                af[mt][1] = __float_as_uint(a.y);
                af[mt][2] = __float_as_uint(a.z);
                af[mt][3] = __float_as_uint(a.w);
            }
            int kr = ks8 << 3;
            #pragma unroll
            for (int nt = 0; nt < 8; nt++) {
                int n = wn + (nt << 3) + g;
                unsigned b0 = f2tf(Bs[buf][(kr + tg) * 136 + n]);
                unsigned b1 = f2tf(Bs[buf][(kr + tg + 4) * 136 + n]);
                #pragma unroll
                for (int mt = 0; mt < 3; mt++)
                    mma8(acc[mt][nt], af[mt], b0, b1);
            }
        }
    };

    const int T = KB8 >> 1;
    issue(0, 0);
    for (int t = 0; t < T; t++) {
        asm volatile("cp.async.wait_group 0;\n");
        __syncthreads();
        if (t + 1 < T) issue(t + 1, (t + 1) & 1);
        compute(t & 1, t);
    }

    #pragma unroll
    for (int mt = 0; mt < 3; mt++)
        #pragma unroll
        for (int nt = 0; nt < 8; nt++) {
            long row = m0 + wm + (mt << 4) + g;
            int col = n0 + wn + (nt << 3) + (tg << 1);
            *reinterpret_cast<float2*>(Cb + row * SP + col) =
                make_float2(acc[mt][nt][0], acc[mt][nt][1]);
            *reinterpret_cast<float2*>(Cb + (row + 8) * SP + col) =
                make_float2(acc[mt][nt][2], acc[mt][nt][3]);
        }
}

// ---------------- depthwise 3x3: barrier-free, register row window, direct L1 loads --------
__global__ void __launch_bounds__(128) dw_v3(const float* __restrict__ dww) {
    int w = threadIdx.x;
    int o = blockIdx.x;
    int b = blockIdx.y;
    const float* src = d_qkv1 + ((long)(b * 576 + o)) * SP;
    float* dst = d_qkvd + ((long)(b * 576 + o)) * SP;
    float wg[9];
    #pragma unroll
    for (int t = 0; t < 9; t++) wg[t] = __ldg(dww + o * 9 + t);
    const bool hl = (w > 0), hr = (w < 127);

    float al = 0.f, am = 0.f, ar = 0.f;
    float bl, bm, br;
    bl = hl ? src[w - 1] : 0.f;
    bm = src[w];
    br = hr ? src[w + 1] : 0.f;

    #pragma unroll 4
    for (int h = 0; h < 128; h++) {
        float cl = 0.f, cm = 0.f, cr = 0.f;
        if (h < 127) {
            const float* r = src + (h + 1) * 128;
            cl = hl ? r[w - 1] : 0.f;
            cm = r[w];
            cr = hr ? r[w + 1] : 0.f;
        }
        float acc = wg[0] * al + wg[1] * am + wg[2] * ar
                  + wg[3] * bl + wg[4] * bm + wg[5] * br
                  + wg[6] * cl + wg[7] * cm + wg[8] * cr;
        dst[h * 128 + w] = acc;
        al = bl; am = bm; ar = br;
        bl = cl; bm = cm; br = cr;
    }
}

// ---------------- merged split-K Gram: one block computes BOTH qk and ck 48x48 blocks ------
// Loads Sq, Sc, Sk per K-step (3 tiles instead of 4 across the old t-pair).
__global__ void __launch_bounds__(128) gram2_kernel() {
    __shared__ unsigned Sq[32 * 56];
    __shared__ unsigned Sc[32 * 56];
    __shared__ unsigned Sk[32 * 56];
    int slice = blockIdx.x;   // 0..7
    int bh = blockIdx.y;      // 0..31
    int b = bh >> 2, h = bh & 3;
    const float* Q = d_qkvd + ((long)(b * 576 + h * 48)) * SP;
    const float* Cn = d_cnf + ((long)(b * 192 + h * 48)) * SP;
    const float* K = d_qkvd + ((long)(b * 576 + 192 + h * 48)) * SP;
    int tid = threadIdx.x;
    int warp = tid >> 5, lane = tid & 31, g = lane >> 2, tg = lane & 3;
    float accq[6][4], accc[6][4];
    #pragma unroll
    for (int i = 0; i < 6; i++)
        #pragma unroll
        for (int j = 0; j < 4; j++) { accq[i][j] = 0.f; accc[i][j] = 0.f; }

    int kbase = slice * 2048;
    for (int kb = 0; kb < 2048; kb += 32) {
        __syncthreads();
        #pragma unroll
        for (int it = 0; it < 12; it++) {
            int idx = tid + it * 128;
            int m = idx >> 5, kk = idx & 31;
            long off = (long)m * SP + kbase + kb + kk;
            Sq[kk * 56 + m] = f2tf(Q[off]);
            Sc[kk * 56 + m] = f2tf(Cn[off]);
            Sk[kk * 56 + m] = f2tf(K[off]);
        }
        __syncthreads();
        if (warp < 3) {
            #pragma unroll
            for (int ks = 0; ks < 32; ks += 8) {
                unsigned aq[4], ac[4];
                int m = warp << 4;
                aq[0] = Sq[(ks + tg) * 56 + m + g];
                aq[1] = Sq[(ks + tg) * 56 + m + g + 8];
                aq[2] = Sq[(ks + tg + 4) * 56 + m + g];
                aq[3] = Sq[(ks + tg + 4) * 56 + m + g + 8];
                ac[0] = Sc[(ks + tg) * 56 + m + g];
                ac[1] = Sc[(ks + tg) * 56 + m + g + 8];
                ac[2] = Sc[(ks + tg + 4) * 56 + m + g];
                ac[3] = Sc[(ks + tg + 4) * 56 + m + g + 8];
                #pragma unroll
                for (int nt = 0; nt < 6; nt++) {
                    unsigned b0 = Sk[(ks + tg) * 56 + (nt << 3) + g];
                    unsigned b1 = Sk[(ks + tg + 4) * 56 + (nt << 3) + g];
                    mma8(accq[nt], aq, b0, b1);
                    mma8(accc[nt], ac, b0, b1);
                }
            }
        }
    }
    if (warp < 3) {
        float* outq = d_gramp + (((long)slice * 2 + 0) * 32 + bh) * 2304;
        float* outc = d_gramp + (((long)slice * 2 + 1) * 32 + bh) * 2304;
        #pragma unroll
        for (int nt = 0; nt < 6; nt++) {
            int r = (warp << 4) + g;
            int col = (nt << 3) + (tg << 1);
            outq[r * 48 + col] = accq[nt][0];
            outq[r * 48 + col + 1] = accq[nt][1];
            outq[(r + 8) * 48 + col] = accq[nt][2];
            outq[(r + 8) * 48 + col + 1] = accq[nt][3];
            outc[r * 48 + col] = accc[nt][0];
            outc[r * 48 + col + 1] = accc[nt][1];
            outc[(r + 8) * 48 + col] = accc[nt][2];
            outc[(r + 8) * 48 + col + 1] = accc[nt][3];
        }
    }
}

__global__ void gram_reduce_kernel() {
    int idx = blockIdx.x * 256 + threadIdx.x;
    if (idx < 2 * 32 * 2304) {
        float s = 0.f;
        #pragma unroll
        for (int p = 0; p < 8; p++) s += d_gramp[(long)p * (2 * 32 * 2304) + idx];
        d_gram[idx] = s;
    }
}

// ---------------- per-(b,c) norms + <q,cn>, float4 loads ----------------
__global__ void diag_kernel() {
    int bc = blockIdx.x;
    int b = bc / 192;
    const float4* q = (const float4*)(d_qkvd + ((long)(b * 576 + (bc - b * 192))) * SP);
    const float4* k = (const float4*)((const float*)q + 192L * SP);
    const float4* cn = (const float4*)(d_cnf + ((long)bc) * SP);
    float s0 = 0, s1 = 0, s2 = 0, s3 = 0;
    for (int i = threadIdx.x; i < SP / 4; i += 256) {
        float4 qv = q[i], kv = k[i], cv = cn[i];
        s0 += qv.x * qv.x + qv.y * qv.y + qv.z * qv.z + qv.w * qv.w;
        s1 += kv.x * kv.x + kv.y * kv.y + kv.z * kv.z + kv.w * kv.w;
        s2 += cv.x * cv.x + cv.y * cv.y + cv.z * cv.z + cv.w * cv.w;
        s3 += qv.x * cv.x + qv.y * cv.y + qv.z * cv.z + qv.w * cv.w;
    }
    __shared__ float red[4][256];
    int tid = threadIdx.x;
    red[0][tid] = s0; red[1][tid] = s1; red[2][tid] = s2; red[3][tid] = s3;
    __syncthreads();
    for (int off = 128; off > 0; off >>= 1) {
        if (tid < off) {
            #pragma unroll
            for (int j = 0; j < 4; j++) red[j][tid] += red[j][tid + off];
        }
        __syncthreads();
    }
    if (tid < 4) d_normv[bc * 4 + tid] = red[tid][0];
}

// ---------------- logits + softmax -> attn ----------------
__global__ void attn_kernel(const float* __restrict__ temp) {
    int bh = blockIdx.x;
    int b = bh >> 2, h = bh & 3;
    __shared__ float L[48][49];
    __shared__ float qn[48], kn[48], cnn[48], un[48];
    int tid = threadIdx.x;
    if (tid < 48) {
        int bc = b * 192 + h * 48 + tid;
        float nq = d_normv[bc * 4 + 0];
        float nk = d_normv[bc * 4 + 1];
        float nc = d_normv[bc * 4 + 2];
        float dqc = d_normv[bc * 4 + 3];
        float q_n = fmaxf(sqrtf(nq), 1e-12f);
        float k_n = fmaxf(sqrtf(nk), 1e-12f);
        float c_n = fmaxf(sqrtf(nc), 1e-12f);
        float uu = 2.f + 2.f * dqc / (q_n * c_n);
        float u_n = fmaxf(sqrtf(fmaxf(uu, 0.f)), 1e-12f);
        qn[tid] = q_n; kn[tid] = k_n; cnn[tid] = c_n; un[tid] = u_n;
    }
    __syncthreads();
    const float* Gqk = d_gram + (long)bh * 2304;
    const float* Gck = d_gram + (long)(32 + bh) * 2304;
    float tp = temp[h];
    for (int idx = tid; idx < 2304; idx += 256) {
        int c = idx / 48, d = idx - c * 48;
        L[c][d] = (Gqk[idx] / qn[c] + Gck[idx] / cnn[c]) / (un[c] * kn[d]) * tp;
    }
    __syncthreads();
    if (tid < 48) {
        float mx = -1e30f;
        #pragma unroll
        for (int d = 0; d < 48; d++) mx = fmaxf(mx, L[tid][d]);
        float e[48];
        float sum = 0.f;
        #pragma unroll
        for (int d = 0; d < 48; d++) { e[d] = expf(L[tid][d] - mx); sum += e[d]; }
        float inv = 1.f / sum;
        #pragma unroll
        for (int d = 0; d < 48; d++)
            d_attn[(long)bh * 2304 + tid * 48 + d] = e[d] * inv;
    }
}

// ---------------- M_b = P * blockdiag(attn_b) in fragment order, tf32-rounded --------------
__global__ void mker_frag(const float* __restrict__ P) {
    int cell = blockIdx.x;
    int lane = threadIdx.x;
    int b = cell / 288; int r = cell - b * 288;
    int mb = r / 24, kb8 = r - mb * 24;
    int g = lane >> 2, tg = lane & 3;
    int o0 = mb * 16 + g;
    int j0 = kb8 * 8 + tg;
    int j1 = j0 + 4;
    float v[4];
    #pragma unroll
    for (int q = 0; q < 4; q++) {
        int o = o0 + ((q & 1) << 3);
        int j = (q < 2) ? j0 : j1;
        int h = j / 48, d = j - h * 48;
        const float* att = d_attn + ((long)(b * 4 + h)) * 2304 + d;
        const float* pw = P + o * 192 + h * 48;
        float acc = 0.f;
        #pragma unroll
        for (int c2 = 0; c2 < 48; c2++) acc += pw[c2] * att[c2 * 48];
        v[q] = f2tff(acc);
    }
    d_MmatF[(long)cell * 32 + lane] = make_float4(v[0], v[1], v[2], v[3]);
}

// ---------------- launch ----------------
extern "C" void kernel_launch(void* const* d_in, const int* in_sizes, int n_in,
                              void* d_out, int out_size) {
    const float* x     = (const float*)d_in[0];
    const float* cn    = (const float*)d_in[1];
    const float* w1    = (const float*)d_in[2];
    const float* w3    = (const float*)d_in[3];
    const float* qkvw  = (const float*)d_in[4];
    const float* dww   = (const float*)d_in[5];
    const float* projw = (const float*)d_in[6];
    const float* temp  = (const float*)d_in[7];
    float* out = (float*)d_out;

    float *pCnf, *pQkv1, *pQkvd;
    float4 *pWqkvF, *pMF;
    cudaGetSymbolAddress((void**)&pCnf, d_cnf);
    cudaGetSymbolAddress((void**)&pQkv1, d_qkv1);
    cudaGetSymbolAddress((void**)&pQkvd, d_qkvd);
    cudaGetSymbolAddress((void**)&pWqkvF, d_WqkvF);
    cudaGetSymbolAddress((void**)&pMF, d_MmatF);

    compose_w_frag<<<2592, 32>>>(w1, w3);
    swz_qkvw<<<864, 32>>>(qkvw);
    pad_kernel<<<dim3(130, 192, 8), 132>>>(cn);
    // fused: cn 3x3 conv (y<2) + qkv 1x1 GEMM (y>=2)
    fat_conv_qkv<<<dim3(128, 8, 8), 128>>>(pWqkvF, x, pCnf, pQkv1);
    dw_v3<<<dim3(576, 8), 128>>>(dww);
    gram2_kernel<<<dim3(8, 32), 128>>>();
    gram_reduce_kernel<<<576, 256>>>();
    diag_kernel<<<1536, 256>>>();
    attn_kernel<<<32, 256>>>(temp);
    mker_frag<<<2304, 32>>>(projw);
    // out = M_b @ v  (v = qkvd channels 384..575), M=192 K=192
    gemm_v4<<<dim3(128, 2, 8), 128>>>(pMF, pQkvd + 384L * SP, out,
                                      24, 12 * 24 * 32, 576L * SP, 192L * SP);
}

// round 17
// speedup vs baseline: 1.8556x; 1.0078x over previous
#include <cuda_runtime.h>
#include <cstdint>
#include <stdint.h>
#include <math.h>

#define SP 16384

// ---------------- scratch (device globals; every element rewritten per call) ----------------
__device__ float4 d_WcF[2592 * 32];                // composite conv weight, fragment order, tf32-rounded
__device__ float4 d_WqkvF[36 * 24 * 32];           // qkv weight, fragment order, tf32-rounded
__device__ float4 d_MmatF[8 * 12 * 24 * 32];       // per-batch P*blockdiag(attn), fragment order
__device__ float d_pad[8L * 192 * 130 * 132];      // zero-padded cn, tf32-rounded, row stride 132 (j=w+1)
__device__ float d_cnf[8L * 192 * SP];             // cn feature
__device__ float d_qkv1[8L * 576 * SP];            // qkv after 1x1
__device__ float d_qkvd[8L * 576 * SP];            // qkv after dw 3x3
__device__ float d_gramp[32L * 2 * 32 * 2304];     // split-K gram partials (32 slices)
__device__ float d_normv[8 * 192 * 4];             // per (b,c): |q|^2, |k|^2, |cn|^2, <q,cn>
__device__ float d_attn[32 * 2304];                // softmax attn per (b,h)

__device__ __forceinline__ unsigned f2tf(float f) {
    unsigned u;
    asm("cvt.rna.tf32.f32 %0, %1;" : "=r"(u) : "f"(f));
    return u;
}
__device__ __forceinline__ float f2tff(float f) { return __uint_as_float(f2tf(f)); }

__device__ __forceinline__ void mma8(float* acc, const unsigned* a, unsigned b0, unsigned b1) {
    asm volatile(
        "mma.sync.aligned.m16n8k8.row.col.f32.tf32.tf32.f32 "
        "{%0,%1,%2,%3}, {%4,%5,%6,%7}, {%8,%9}, {%0,%1,%2,%3};\n"
        : "+f"(acc[0]), "+f"(acc[1]), "+f"(acc[2]), "+f"(acc[3])
        : "r"(a[0]), "r"(a[1]), "r"(a[2]), "r"(a[3]), "r"(b0), "r"(b1));
}

__device__ __forceinline__ void cpa16(float* smem, const float* g) {
    unsigned d = (unsigned)__cvta_generic_to_shared(smem);
    asm volatile("cp.async.cg.shared.global [%0], [%1], 16;\n" :: "r"(d), "l"(g));
}

// ---------------- composite conv weight, fragment order ----------------
__global__ void compose_w_frag(const float* __restrict__ w1, const float* __restrict__ w3) {
    int cell = blockIdx.x;
    int lane = threadIdx.x;
    int ks8 = cell & 1;
    int c2 = cell >> 1;
    int dx = c2 % 3;  int c3 = c2 / 3;
    int cib = c3 % 12; int c4 = c3 / 12;
    int dy = c4 % 3;  int mb = c4 / 3;
    int g = lane >> 2, tg = lane & 3;
    int tap = dy * 3 + dx;
    int o0 = mb * 16 + g;
    int ci0 = cib * 16 + ks8 * 8 + tg;
    float s0 = 0, s1 = 0, s2 = 0, s3 = 0;
    for (int m = 0; m < 192; m++) {
        float a0 = w3[(o0 * 192 + m) * 9 + tap];
        float a1 = w3[((o0 + 8) * 192 + m) * 9 + tap];
        float b0 = w1[m * 192 + ci0];
        float b1 = w1[m * 192 + ci0 + 4];
        s0 += a0 * b0; s1 += a1 * b0; s2 += a0 * b1; s3 += a1 * b1;
    }
    d_WcF[cell * 32 + lane] = make_float4(f2tff(s0), f2tff(s1), f2tff(s2), f2tff(s3));
}

// ---------------- qkv weight fragment swizzle ----------------
__global__ void swz_qkvw(const float* __restrict__ w) {
    int mb = blockIdx.x / 24, kb8 = blockIdx.x % 24;
    int lane = threadIdx.x;
    int g = lane >> 2, tg = lane & 3;
    int o0 = mb * 16 + g, k0 = kb8 * 8 + tg;
    float4 v;
    v.x = f2tff(w[o0 * 192 + k0]);
    v.y = f2tff(w[(o0 + 8) * 192 + k0]);
    v.z = f2tff(w[o0 * 192 + k0 + 4]);
    v.w = f2tff(w[(o0 + 8) * 192 + k0 + 4]);
    d_WqkvF[(mb * 24 + kb8) * 32 + lane] = v;
}

// ---------------- zero-padded tf32-rounded copy of cn: [b][c][130][132], j = w+1 -----------
__global__ void pad_kernel(const float* __restrict__ cn) {
    int j = threadIdx.x;      // 0..131
    int hh = blockIdx.x;      // 0..129
    int c = blockIdx.y;
    int b = blockIdx.z;
    float v = 0.f;
    if (hh >= 1 && hh <= 128 && j >= 1 && j <= 128)
        v = f2tff(cn[((long)(b * 192 + c)) * SP + (hh - 1) * 128 + (j - 1)]);
    d_pad[(((long)(b * 192 + c)) * 130 + hh) * 132 + j] = v;
}

// ---------------- FAT kernel: conv (y<2) + qkv 1x1 GEMM (y>=2) in one grid ----------------
__global__ void __launch_bounds__(128, 3) fat_conv_qkv(
    const float4* __restrict__ WqkvF, const float* __restrict__ x,
    float* __restrict__ Ccnf, float* __restrict__ Cqkv)
{
    __shared__ float Bs[2][16 * 136];

    const int bz = blockIdx.z;
    const int tid = threadIdx.x;
    const int warp = tid >> 5, lane = tid & 31;
    const int g = lane >> 2, tg = lane & 3;
    const int wm = (warp >> 1) * 48;
    const int wn = (warp & 1) << 6;
    const int mwb = (warp >> 1) * 3;

    float acc[3][8][4];
    #pragma unroll
    for (int i = 0; i < 3; i++)
        #pragma unroll
        for (int j = 0; j < 8; j++)
            #pragma unroll
            for (int l = 0; l < 4; l++) acc[i][j][l] = 0.f;

    if (blockIdx.y < 2) {
        // ===== conv branch =====
        const int h_row = blockIdx.x;
        const int n0 = h_row << 7;
        const int m0 = blockIdx.y * 96;
        const int mb0 = blockIdx.y * 6;
        float* Cb = Ccnf + (long)bz * 192 * SP;

        auto issueB = [&](int gg, int buf) {
            int dy = gg / 12;
            int ci0 = (gg - dy * 12) << 4;
            const float* base = d_pad + (((long)(bz * 192 + ci0)) * 130 + h_row + dy) * 132;
            #pragma unroll
            for (int it = 0; it < 5; it++) {
                int idx = tid + (it << 7);
                if (idx < 528) {
                    int kr = idx / 33;
                    int q = (idx - kr * 33) << 2;
                    cpa16(&Bs[buf][kr * 136 + q], base + (long)kr * (130 * 132) + q);
                }
            }
            asm volatile("cp.async.commit_group;\n");
        };

        auto pass = [&](int buf, int dy, int cib, int dx) {
            #pragma unroll
            for (int ks8 = 0; ks8 < 2; ks8++) {
                unsigned af[3][4];
                #pragma unroll
                for (int mt = 0; mt < 3; mt++) {
                    int cell = ((((mb0 + mwb + mt) * 3 + dy) * 12 + cib) * 3 + dx) * 2 + ks8;
                    float4 a = d_WcF[cell * 32 + lane];
                    af[mt][0] = __float_as_uint(a.x);
                    af[mt][1] = __float_as_uint(a.y);
                    af[mt][2] = __float_as_uint(a.z);
                    af[mt][3] = __float_as_uint(a.w);
                }
                int kr = ks8 << 3;
                #pragma unroll
                for (int nt = 0; nt < 8; nt++) {
                    int n = wn + (nt << 3) + g + dx;
                    unsigned b0 = __float_as_uint(Bs[buf][(kr + tg) * 136 + n]);
                    unsigned b1 = __float_as_uint(Bs[buf][(kr + tg + 4) * 136 + n]);
                    #pragma unroll
                    for (int mt = 0; mt < 3; mt++)
                        mma8(acc[mt][nt], af[mt], b0, b1);
                }
            }
        };

        issueB(0, 0);
        for (int gg = 0; gg < 36; gg++) {
            asm volatile("cp.async.wait_group 0;\n");
            __syncthreads();
            if (gg + 1 < 36) issueB(gg + 1, (gg + 1) & 1);
            int dy = gg / 12;
            int cib = gg - dy * 12;
            pass(gg & 1, dy, cib, 0);
            pass(gg & 1, dy, cib, 1);
            pass(gg & 1, dy, cib, 2);
        }

        #pragma unroll
        for (int mt = 0; mt < 3; mt++)
            #pragma unroll
            for (int nt = 0; nt < 8; nt++) {
                long row = m0 + wm + (mt << 4) + g;
                int col = n0 + wn + (nt << 3) + (tg << 1);
                *reinterpret_cast<float2*>(Cb + row * SP + col) =
                    make_float2(acc[mt][nt][0], acc[mt][nt][1]);
                *reinterpret_cast<float2*>(Cb + (row + 8) * SP + col) =
                    make_float2(acc[mt][nt][2], acc[mt][nt][3]);
            }
    } else {
        // ===== qkv 1x1 GEMM branch: M=576 K=192 (KB8=24) =====
        const int n0 = blockIdx.x << 7;
        const int m0 = (blockIdx.y - 2) * 96;
        const int mb0 = (blockIdx.y - 2) * 6;
        const float* Bb = x + (long)bz * 192 * SP;
        float* Cb = Cqkv + (long)bz * 576 * SP;
        const int bk = tid >> 4;
        const int bn = (tid & 15) << 3;

        auto issue = [&](int t, int buf) {
            int k0 = t << 4;
            #pragma unroll
            for (int i = 0; i < 2; i++) {
                int kr = bk + (i << 3);
                const float* p = Bb + (long)(k0 + kr) * SP + n0 + bn;
                cpa16(&Bs[buf][kr * 136 + bn], p);
                cpa16(&Bs[buf][kr * 136 + bn + 4], p + 4);
            }
            asm volatile("cp.async.commit_group;\n");
        };

        auto compute = [&](int buf, int t) {
            #pragma unroll
            for (int ks8 = 0; ks8 < 2; ks8++) {
                int kb8 = (t << 1) + ks8;
                unsigned af[3][4];
                #pragma unroll
                for (int mt = 0; mt < 3; mt++) {
                    float4 a = WqkvF[((mb0 + mwb + mt) * 24 + kb8) * 32 + lane];
                    af[mt][0] = __float_as_uint(a.x);
                    af[mt][1] = __float_as_uint(a.y);
                    af[mt][2] = __float_as_uint(a.z);
                    af[mt][3] = __float_as_uint(a.w);
                }
                int kr = ks8 << 3;
                #pragma unroll
                for (int nt = 0; nt < 8; nt++) {
                    int n = wn + (nt << 3) + g;
                    unsigned b0 = f2tf(Bs[buf][(kr + tg) * 136 + n]);
                    unsigned b1 = f2tf(Bs[buf][(kr + tg + 4) * 136 + n]);
                    #pragma unroll
                    for (int mt = 0; mt < 3; mt++)
                        mma8(acc[mt][nt], af[mt], b0, b1);
                }
            }
        };

        issue(0, 0);
        for (int t = 0; t < 12; t++) {
            asm volatile("cp.async.wait_group 0;\n");
            __syncthreads();
            if (t + 1 < 12) issue(t + 1, (t + 1) & 1);
            compute(t & 1, t);
        }

        #pragma unroll
        for (int mt = 0; mt < 3; mt++)
            #pragma unroll
            for (int nt = 0; nt < 8; nt++) {
                long row = m0 + wm + (mt << 4) + g;
                int col = n0 + wn + (nt << 3) + (tg << 1);
                *reinterpret_cast<float2*>(Cb + row * SP + col) =
                    make_float2(acc[mt][nt][0], acc[mt][nt][1]);
                *reinterpret_cast<float2*>(Cb + (row + 8) * SP + col) =
                    make_float2(acc[mt][nt][2], acc[mt][nt][3]);
            }
    }
}

// ---------------- dense tf32 GEMM v4 (final M_b @ v) ----------------
__global__ void __launch_bounds__(128, 3) gemm_v4(
    const float4* __restrict__ Af, const float* __restrict__ B, float* __restrict__ C,
    int KB8, long sAf, long sB, long sC)
{
    __shared__ float Bs[2][16 * 136];

    const int bz = blockIdx.z;
    const int n0 = blockIdx.x << 7;
    const int m0 = blockIdx.y * 96;
    const int mb0 = blockIdx.y * 6;
    const int tid = threadIdx.x;
    const float4* Ab = Af + (long)bz * sAf;
    const float* Bb = B + (long)bz * sB;
    float* Cb = C + (long)bz * sC;

    const int bk = tid >> 4;
    const int bn = (tid & 15) << 3;
    const int warp = tid >> 5, lane = tid & 31;
    const int wm = (warp >> 1) * 48;
    const int wn = (warp & 1) << 6;
    const int g = lane >> 2, tg = lane & 3;
    const int mwb = (warp >> 1) * 3;

    float acc[3][8][4];
    #pragma unroll
    for (int i = 0; i < 3; i++)
        #pragma unroll
        for (int j = 0; j < 8; j++)
            #pragma unroll
            for (int l = 0; l < 4; l++) acc[i][j][l] = 0.f;

    auto issue = [&](int t, int buf) {
        int k0 = t << 4;
        #pragma unroll
        for (int i = 0; i < 2; i++) {
            int kr = bk + (i << 3);
            const float* p = Bb + (long)(k0 + kr) * SP + n0 + bn;
            cpa16(&Bs[buf][kr * 136 + bn], p);
            cpa16(&Bs[buf][kr * 136 + bn + 4], p + 4);
        }
        asm volatile("cp.async.commit_group;\n");
    };

    auto compute = [&](int buf, int t) {
        #pragma unroll
        for (int ks8 = 0; ks8 < 2; ks8++) {
            int kb8 = (t << 1) + ks8;
            unsigned af[3][4];
            #pragma unroll
            for (int mt = 0; mt < 3; mt++) {
                float4 a = Ab[((mb0 + mwb + mt) * KB8 + kb8) * 32 + lane];
                af[mt][0] = __float_as_uint(a.x);
                af[mt][1] = __float_as_uint(a.y);
                af[mt][2] = __float_as_uint(a.z);
                af[mt][3] = __float_as_uint(a.w);
            }
            int kr = ks8 << 3;
            #pragma unroll
            for (int nt = 0; nt < 8; nt++) {
                int n = wn + (nt << 3) + g;
                unsigned b0 = f2tf(Bs[buf][(kr + tg) * 136 + n]);
                unsigned b1 = f2tf(Bs[buf][(kr + tg + 4) * 136 + n]);
                #pragma unroll
                for (int mt = 0; mt < 3; mt++)
                    mma8(acc[mt][nt], af[mt], b0, b1);
            }
        }
    };

    const int T = KB8 >> 1;
    issue(0, 0);
    for (int t = 0; t < T; t++) {
        asm volatile("cp.async.wait_group 0;\n");
        __syncthreads();
        if (t + 1 < T) issue(t + 1, (t + 1) & 1);
        compute(t & 1, t);
    }

    #pragma unroll
    for (int mt = 0; mt < 3; mt++)
        #pragma unroll
        for (int nt = 0; nt < 8; nt++) {
            long row = m0 + wm + (mt << 4) + g;
            int col = n0 + wn + (nt << 3) + (tg << 1);
            *reinterpret_cast<float2*>(Cb + row * SP + col) =
                make_float2(acc[mt][nt][0], acc[mt][nt][1]);
            *reinterpret_cast<float2*>(Cb + (row + 8) * SP + col) =
                make_float2(acc[mt][nt][2], acc[mt][nt][3]);
        }
}

// ---------------- depthwise 3x3 + fused diag sums (replaces diag_kernel) ------------------
// q-blocks (o<192): accumulate q^2, q*cn, cn^2 ; k-blocks (192<=o<384): k^2 ; v: none.
__global__ void __launch_bounds__(128) dw_v4(const float* __restrict__ dww) {
    int w = threadIdx.x;
    int o = blockIdx.x;
    int b = blockIdx.y;
    const float* src = d_qkv1 + ((long)(b * 576 + o)) * SP;
    float* dst = d_qkvd + ((long)(b * 576 + o)) * SP;
    const bool isq = (o < 192);
    const bool isk = (o >= 192) && (o < 384);
    const float* cnsrc = d_cnf + ((long)(b * 192 + (isq ? o : 0))) * SP;
    float wg[9];
    #pragma unroll
    for (int t = 0; t < 9; t++) wg[t] = __ldg(dww + o * 9 + t);
    const bool hl = (w > 0), hr = (w < 127);

    float s0 = 0.f, s1 = 0.f, s2 = 0.f;
    float al = 0.f, am = 0.f, ar = 0.f;
    float bl, bm, br;
    bl = hl ? src[w - 1] : 0.f;
    bm = src[w];
    br = hr ? src[w + 1] : 0.f;

    #pragma unroll 4
    for (int h = 0; h < 128; h++) {
        float cl = 0.f, cm = 0.f, cr = 0.f;
        if (h < 127) {
            const float* r = src + (h + 1) * 128;
            cl = hl ? r[w - 1] : 0.f;
            cm = r[w];
            cr = hr ? r[w + 1] : 0.f;
        }
        float acc = wg[0] * al + wg[1] * am + wg[2] * ar
                  + wg[3] * bl + wg[4] * bm + wg[5] * br
                  + wg[6] * cl + wg[7] * cm + wg[8] * cr;
        dst[h * 128 + w] = acc;
        if (isq) {
            float cv = cnsrc[h * 128 + w];
            s0 += acc * acc; s1 += acc * cv; s2 += cv * cv;
        } else if (isk) {
            s0 += acc * acc;
        }
        al = bl; am = bm; ar = br;
        bl = cl; bm = cm; br = cr;
    }

    if (isq || isk) {
        __shared__ float red[3][128];
        red[0][w] = s0; red[1][w] = s1; red[2][w] = s2;
        __syncthreads();
        for (int off = 64; off > 0; off >>= 1) {
            if (w < off) {
                red[0][w] += red[0][w + off];
                red[1][w] += red[1][w + off];
                red[2][w] += red[2][w + off];
            }
            __syncthreads();
        }
        if (w == 0) {
            if (isq) {
                int bc = b * 192 + o;
                d_normv[bc * 4 + 0] = red[0][0];
                d_normv[bc * 4 + 3] = red[1][0];
                d_normv[bc * 4 + 2] = red[2][0];
            } else {
                int bc = b * 192 + (o - 192);
                d_normv[bc * 4 + 1] = red[0][0];
            }
        }
    }
}

// ---------------- merged split-K Gram, 32 slices: both qk and ck 48x48 blocks --------------
__global__ void __launch_bounds__(128) gram2_kernel() {
    __shared__ unsigned Sq[32 * 56];
    __shared__ unsigned Sc[32 * 56];
    __shared__ unsigned Sk[32 * 56];
    int slice = blockIdx.x;   // 0..31
    int bh = blockIdx.y;      // 0..31
    int b = bh >> 2, h = bh & 3;
    const float* Q = d_qkvd + ((long)(b * 576 + h * 48)) * SP;
    const float* Cn = d_cnf + ((long)(b * 192 + h * 48)) * SP;
    const float* K = d_qkvd + ((long)(b * 576 + 192 + h * 48)) * SP;
    int tid = threadIdx.x;
    int warp = tid >> 5, lane = tid & 31, g = lane >> 2, tg = lane & 3;
    float accq[6][4], accc[6][4];
    #pragma unroll
    for (int i = 0; i < 6; i++)
        #pragma unroll
        for (int j = 0; j < 4; j++) { accq[i][j] = 0.f; accc[i][j] = 0.f; }

    int kbase = slice * 512;
    for (int kb = 0; kb < 512; kb += 32) {
        __syncthreads();
        #pragma unroll
        for (int it = 0; it < 12; it++) {
            int idx = tid + it * 128;
            int m = idx >> 5, kk = idx & 31;
            long off = (long)m * SP + kbase + kb + kk;
            Sq[kk * 56 + m] = f2tf(Q[off]);
            Sc[kk * 56 + m] = f2tf(Cn[off]);
            Sk[kk * 56 + m] = f2tf(K[off]);
        }
        __syncthreads();
        if (warp < 3) {
            #pragma unroll
            for (int ks = 0; ks < 32; ks += 8) {
                unsigned aq[4], ac[4];
                int m = warp << 4;
                aq[0] = Sq[(ks + tg) * 56 + m + g];
                aq[1] = Sq[(ks + tg) * 56 + m + g + 8];
                aq[2] = Sq[(ks + tg + 4) * 56 + m + g];
                aq[3] = Sq[(ks + tg + 4) * 56 + m + g + 8];
                ac[0] = Sc[(ks + tg) * 56 + m + g];
                ac[1] = Sc[(ks + tg) * 56 + m + g + 8];
                ac[2] = Sc[(ks + tg + 4) * 56 + m + g];
                ac[3] = Sc[(ks + tg + 4) * 56 + m + g + 8];
                #pragma unroll
                for (int nt = 0; nt < 6; nt++) {
                    unsigned b0 = Sk[(ks + tg) * 56 + (nt << 3) + g];
                    unsigned b1 = Sk[(ks + tg + 4) * 56 + (nt << 3) + g];
                    mma8(accq[nt], aq, b0, b1);
                    mma8(accc[nt], ac, b0, b1);
                }
            }
        }
    }
    if (warp < 3) {
        float* outq = d_gramp + (((long)slice * 2 + 0) * 32 + bh) * 2304;
        float* outc = d_gramp + (((long)slice * 2 + 1) * 32 + bh) * 2304;
        #pragma unroll
        for (int nt = 0; nt < 6; nt++) {
            int r = (warp << 4) + g;
            int col = (nt << 3) + (tg << 1);
            outq[r * 48 + col] = accq[nt][0];
            outq[r * 48 + col + 1] = accq[nt][1];
            outq[(r + 8) * 48 + col] = accq[nt][2];
            outq[(r + 8) * 48 + col + 1] = accq[nt][3];
            outc[r * 48 + col] = accc[nt][0];
            outc[r * 48 + col + 1] = accc[nt][1];
            outc[(r + 8) * 48 + col] = accc[nt][2];
            outc[(r + 8) * 48 + col + 1] = accc[nt][3];
        }
    }
}

// ---------------- logits + softmax -> attn (inline 32-slice reduction) ----------------
__global__ void attn_kernel(const float* __restrict__ temp) {
    int bh = blockIdx.x;
    int b = bh >> 2, h = bh & 3;
    __shared__ float L[48][49];
    __shared__ float qn[48], kn[48], cnn[48], un[48];
    int tid = threadIdx.x;
    if (tid < 48) {
        int bc = b * 192 + h * 48 + tid;
        float nq = d_normv[bc * 4 + 0];
        float nk = d_normv[bc * 4 + 1];
        float nc = d_normv[bc * 4 + 2];
        float dqc = d_normv[bc * 4 + 3];
        float q_n = fmaxf(sqrtf(nq), 1e-12f);
        float k_n = fmaxf(sqrtf(nk), 1e-12f);
        float c_n = fmaxf(sqrtf(nc), 1e-12f);
        float uu = 2.f + 2.f * dqc / (q_n * c_n);
        float u_n = fmaxf(sqrtf(fmaxf(uu, 0.f)), 1e-12f);
        qn[tid] = q_n; kn[tid] = k_n; cnn[tid] = c_n; un[tid] = u_n;
    }
    __syncthreads();
    float tp = temp[h];
    const long sstride = 2L * 32 * 2304;
    for (int idx = tid; idx < 2304; idx += 256) {
        float sq = 0.f, sc = 0.f;
        const float* pq = d_gramp + ((long)bh) * 2304 + idx;
        const float* pc = d_gramp + ((long)(32 + bh)) * 2304 + idx;
        #pragma unroll 8
        for (int p = 0; p < 32; p++) {
            sq += pq[p * sstride];
            sc += pc[p * sstride];
        }
        int c = idx / 48, d = idx - c * 48;
        L[c][d] = (sq / qn[c] + sc / cnn[c]) / (un[c] * kn[d]) * tp;
    }
    __syncthreads();
    if (tid < 48) {
        float mx = -1e30f;
        #pragma unroll
        for (int d = 0; d < 48; d++) mx = fmaxf(mx, L[tid][d]);
        float e[48];
        float sum = 0.f;
        #pragma unroll
        for (int d = 0; d < 48; d++) { e[d] = expf(L[tid][d] - mx); sum += e[d]; }
        float inv = 1.f / sum;
        #pragma unroll
        for (int d = 0; d < 48; d++)
            d_attn[(long)bh * 2304 + tid * 48 + d] = e[d] * inv;
    }
}

// ---------------- M_b = P * blockdiag(attn_b) in fragment order, tf32-rounded --------------
__global__ void mker_frag(const float* __restrict__ P) {
    int cell = blockIdx.x;
    int lane = threadIdx.x;
    int b = cell / 288; int r = cell - b * 288;
    int mb = r / 24, kb8 = r - mb * 24;
    int g = lane >> 2, tg = lane & 3;
    int o0 = mb * 16 + g;
    int j0 = kb8 * 8 + tg;
    int j1 = j0 + 4;
    float v[4];
    #pragma unroll
    for (int q = 0; q < 4; q++) {
        int o = o0 + ((q & 1) << 3);
        int j = (q < 2) ? j0 : j1;
        int h = j / 48, d = j - h * 48;
        const float* att = d_attn + ((long)(b * 4 + h)) * 2304 + d;
        const float* pw = P + o * 192 + h * 48;
        float acc = 0.f;
        #pragma unroll
        for (int c2 = 0; c2 < 48; c2++) acc += pw[c2] * att[c2 * 48];
        v[q] = f2tff(acc);
    }
    d_MmatF[(long)cell * 32 + lane] = make_float4(v[0], v[1], v[2], v[3]);
}

// ---------------- launch ----------------
extern "C" void kernel_launch(void* const* d_in, const int* in_sizes, int n_in,
                              void* d_out, int out_size) {
    const float* x     = (const float*)d_in[0];
    const float* cn    = (const float*)d_in[1];
    const float* w1    = (const float*)d_in[2];
    const float* w3    = (const float*)d_in[3];
    const float* qkvw  = (const float*)d_in[4];
    const float* dww   = (const float*)d_in[5];
    const float* projw = (const float*)d_in[6];
    const float* temp  = (const float*)d_in[7];
    float* out = (float*)d_out;

    float *pCnf, *pQkv1, *pQkvd;
    float4 *pWqkvF, *pMF;
    cudaGetSymbolAddress((void**)&pCnf, d_cnf);
    cudaGetSymbolAddress((void**)&pQkv1, d_qkv1);
    cudaGetSymbolAddress((void**)&pQkvd, d_qkvd);
    cudaGetSymbolAddress((void**)&pWqkvF, d_WqkvF);
    cudaGetSymbolAddress((void**)&pMF, d_MmatF);

    compose_w_frag<<<2592, 32>>>(w1, w3);
    swz_qkvw<<<864, 32>>>(qkvw);
    pad_kernel<<<dim3(130, 192, 8), 132>>>(cn);
    // fused: cn 3x3 conv (y<2) + qkv 1x1 GEMM (y>=2)
    fat_conv_qkv<<<dim3(128, 8, 8), 128>>>(pWqkvF, x, pCnf, pQkv1);
    dw_v4<<<dim3(576, 8), 128>>>(dww);
    gram2_kernel<<<dim3(32, 32), 128>>>();
    attn_kernel<<<32, 256>>>(temp);
    mker_frag<<<2304, 32>>>(projw);
    // out = M_b @ v  (v = qkvd channels 384..575), M=192 K=192
    gemm_v4<<<dim3(128, 2, 8), 128>>>(pMF, pQkvd + 384L * SP, out,
                                      24, 12 * 24 * 32, 576L * SP, 192L * SP);
}